// round 2
// baseline (speedup 1.0000x reference)
#include <cuda_runtime.h>
#include <cstdint>

#define N_NODES 50000
#define N_EDGES 800000
#define DIM     128

// ---------------- scratch (device globals; no allocation allowed) ----------------
__device__ float g_xbuf[N_NODES * DIM];   // current node features
__device__ float g_h   [N_NODES * DIM];   // hidden / predictor A
__device__ float g_aggr[N_NODES * DIM];   // message aggregation
__device__ float g_B   [N_NODES * DIM];   // predictor B
__device__ int   g_src [N_EDGES];
__device__ int   g_dst [N_EDGES];
__device__ int   g_is64;

__device__ __forceinline__ float* bufptr(int id) {
    switch (id) {
        case 0:  return g_xbuf;
        case 1:  return g_h;
        case 2:  return g_aggr;
        default: return g_B;
    }
}

// ---------------- packed f32x2 helpers (Blackwell) ----------------
__device__ __forceinline__ unsigned long long pack2b(float a) {
    unsigned long long r;
    asm("mov.b64 %0, {%1, %1};" : "=l"(r) : "f"(a));
    return r;
}
__device__ __forceinline__ unsigned long long fma2(unsigned long long a,
                                                   unsigned long long b,
                                                   unsigned long long c) {
    unsigned long long d;
    asm("fma.rn.f32x2 %0, %1, %2, %3;" : "=l"(d) : "l"(a), "l"(b), "l"(c));
    return d;
}

// ---------------- dtype detect + index normalize ----------------
__global__ void k_detect(const void* ei) {
    __shared__ int s;
    if (threadIdx.x == 0) s = 0;
    __syncthreads();
    const unsigned* w = (const unsigned*)ei;
    if (w[2 * threadIdx.x + 1] != 0u) atomicOr(&s, 1);
    __syncthreads();
    if (threadIdx.x == 0) g_is64 = (s == 0) ? 1 : 0;
}

__global__ void k_convert(const void* ei) {
    int i = blockIdx.x * blockDim.x + threadIdx.x;
    if (i >= N_EDGES) return;
    if (g_is64) {
        const long long* p = (const long long*)ei;
        g_src[i] = (int)p[i];
        g_dst[i] = (int)p[N_EDGES + i];
    } else {
        const int* p = (const int*)ei;
        g_src[i] = p[i];
        g_dst[i] = p[N_EDGES + i];
    }
}

// ---------------- utility kernels ----------------
__global__ void k_copy_x(const float4* __restrict__ x) {
    float4* o = (float4*)g_xbuf;
    int total = N_NODES * DIM / 4;
    for (int i = blockIdx.x * blockDim.x + threadIdx.x; i < total;
         i += gridDim.x * blockDim.x)
        o[i] = x[i];
}

__global__ void k_zero_aggr() {
    float4* o = (float4*)g_aggr;
    float4 z = make_float4(0.f, 0.f, 0.f, 0.f);
    int total = N_NODES * DIM / 4;
    for (int i = blockIdx.x * blockDim.x + threadIdx.x; i < total;
         i += gridDim.x * blockDim.x)
        o[i] = z;
}

// ---------------- edge message + scatter-add ----------------
__global__ void k_edge_msg(const float* __restrict__ ea,
                           const float* __restrict__ We,
                           const float* __restrict__ be) {
    int gt   = blockIdx.x * blockDim.x + threadIdx.x;
    int warp = gt >> 5;
    int lane = gt & 31;
    int nw   = (gridDim.x * blockDim.x) >> 5;

    float4 wv = ((const float4*)We)[lane];
    float4 bv = ((const float4*)be)[lane];

    for (int e = warp; e < N_EDGES; e += nw) {
        int   s = g_src[e];
        int   d = g_dst[e];
        float a = __ldg(ea + e);
        float4 x = ((const float4*)(g_xbuf + (size_t)s * DIM))[lane];
        float4 m;
        m.x = fmaxf(x.x + fmaf(a, wv.x, bv.x), 0.f);
        m.y = fmaxf(x.y + fmaf(a, wv.y, bv.y), 0.f);
        m.z = fmaxf(x.z + fmaf(a, wv.z, bv.z), 0.f);
        m.w = fmaxf(x.w + fmaf(a, wv.w, bv.w), 0.f);
        float* p = g_aggr + (size_t)d * DIM + lane * 4;
        asm volatile("red.global.add.v4.f32 [%0], {%1,%2,%3,%4};"
                     :: "l"(p), "f"(m.x), "f"(m.y), "f"(m.z), "f"(m.w)
                     : "memory");
    }
}

// ---------------- 128x128 GEMM, thread-per-row, W in smem, f32x2 packed ----------------
// out[row] = act( (A[row] (+ Add[row])) @ W + bias )
__global__ void __launch_bounds__(128)
k_gemm128(int ia, int iadd, const float* __restrict__ W,
          const float* __restrict__ bias, int io, int relu, int nrows) {
    extern __shared__ float sW[];  // 128*128 floats = 64 KB
    const float4* Wv  = (const float4*)W;
    float4*       sWv = (float4*)sW;
    #pragma unroll
    for (int i = 0; i < 32; i++)
        sWv[i * 128 + threadIdx.x] = Wv[i * 128 + threadIdx.x];
    __syncthreads();

    int row = blockIdx.x * 128 + threadIdx.x;
    if (row >= nrows) return;

    const float* A   = bufptr(ia);
    float*       out = bufptr(io);

    float in[DIM];
    {
        const float4* a4 = (const float4*)(A + (size_t)row * DIM);
        #pragma unroll
        for (int k4 = 0; k4 < 32; k4++) {
            float4 v = a4[k4];
            in[4 * k4 + 0] = v.x; in[4 * k4 + 1] = v.y;
            in[4 * k4 + 2] = v.z; in[4 * k4 + 3] = v.w;
        }
        if (iadd >= 0) {
            const float4* b4 = (const float4*)(bufptr(iadd) + (size_t)row * DIM);
            #pragma unroll
            for (int k4 = 0; k4 < 32; k4++) {
                float4 v = b4[k4];
                in[4 * k4 + 0] += v.x; in[4 * k4 + 1] += v.y;
                in[4 * k4 + 2] += v.z; in[4 * k4 + 3] += v.w;
            }
        }
    }

    float2* o2 = (float2*)(out + (size_t)row * DIM);
    #pragma unroll 1
    for (int j0 = 0; j0 < DIM; j0 += 16) {
        unsigned long long acc[8];
        if (bias) {
            const unsigned long long* b2 = (const unsigned long long*)(bias + j0);
            #pragma unroll
            for (int i = 0; i < 8; i++) acc[i] = b2[i];
        } else {
            #pragma unroll
            for (int i = 0; i < 8; i++) acc[i] = 0ull;
        }
        #pragma unroll
        for (int k = 0; k < DIM; k++) {
            unsigned long long a2 = pack2b(in[k]);
            const ulonglong2* wp = (const ulonglong2*)(sW + k * DIM + j0);
            ulonglong2 w0 = wp[0], w1 = wp[1], w2 = wp[2], w3 = wp[3];
            acc[0] = fma2(a2, w0.x, acc[0]);
            acc[1] = fma2(a2, w0.y, acc[1]);
            acc[2] = fma2(a2, w1.x, acc[2]);
            acc[3] = fma2(a2, w1.y, acc[3]);
            acc[4] = fma2(a2, w2.x, acc[4]);
            acc[5] = fma2(a2, w2.y, acc[5]);
            acc[6] = fma2(a2, w3.x, acc[6]);
            acc[7] = fma2(a2, w3.y, acc[7]);
        }
        #pragma unroll
        for (int i = 0; i < 8; i++) {
            float2 v = *(float2*)&acc[i];
            if (relu) { v.x = fmaxf(v.x, 0.f); v.y = fmaxf(v.y, 0.f); }
            o2[j0 / 2 + i] = v;
        }
    }
}

// ---------------- edge predictor epilogue ----------------
__global__ void k_edge_pred(const float* __restrict__ bp1,
                            const float* __restrict__ Wp2,
                            const float* __restrict__ bp2,
                            float* __restrict__ out) {
    int gt   = blockIdx.x * blockDim.x + threadIdx.x;
    int warp = gt >> 5;
    int lane = gt & 31;
    int nw   = (gridDim.x * blockDim.x) >> 5;

    float4 b1 = ((const float4*)bp1)[lane];
    float4 w2 = ((const float4*)Wp2)[lane];
    float  b2 = __ldg(bp2);

    for (int e = warp; e < N_EDGES; e += nw) {
        int s = g_src[e];
        int d = g_dst[e];
        float4 av = ((const float4*)(g_h + (size_t)s * DIM))[lane];
        float4 bv = ((const float4*)(g_B + (size_t)d * DIM))[lane];
        float p = 0.f;
        p = fmaf(fmaxf(av.x + bv.x + b1.x, 0.f), w2.x, p);
        p = fmaf(fmaxf(av.y + bv.y + b1.y, 0.f), w2.y, p);
        p = fmaf(fmaxf(av.z + bv.z + b1.z, 0.f), w2.z, p);
        p = fmaf(fmaxf(av.w + bv.w + b1.w, 0.f), w2.w, p);
        #pragma unroll
        for (int o = 16; o > 0; o >>= 1)
            p += __shfl_xor_sync(0xffffffffu, p, o);
        if (lane == 0) out[e] = p + b2;
    }
}

// ---------------- launch ----------------
extern "C" void kernel_launch(void* const* d_in, const int* in_sizes, int n_in,
                              void* d_out, int out_size) {
    const float* x   = (const float*)d_in[0];
    const float* ea  = (const float*)d_in[1];
    const void*  ei  = d_in[2];
    const float* Wl1 = (const float*)d_in[3];
    const float* bl1 = (const float*)d_in[4];
    const float* Wl2 = (const float*)d_in[5];
    const float* bl2 = (const float*)d_in[6];
    const float* We  = (const float*)d_in[7];
    const float* be  = (const float*)d_in[8];
    const float* Wp1 = (const float*)d_in[9];
    const float* bp1 = (const float*)d_in[10];
    const float* Wp2 = (const float*)d_in[11];
    const float* bp2 = (const float*)d_in[12];
    float* out = (float*)d_out;

    cudaFuncSetAttribute(k_gemm128, cudaFuncAttributeMaxDynamicSharedMemorySize,
                         DIM * DIM * (int)sizeof(float));

    const int GEMM_SMEM  = DIM * DIM * (int)sizeof(float);
    const int GEMM_GRID  = (N_NODES + 127) / 128;      // 391
    const int EDGE_GRID  = 1184;
    const int CONV_GRID  = (N_EDGES + 255) / 256;

    k_detect<<<1, 64>>>(ei);
    k_convert<<<CONV_GRID, 256>>>(ei);
    k_copy_x<<<2048, 256>>>((const float4*)x);

    for (int l = 0; l < 3; l++) {
        k_zero_aggr<<<2048, 256>>>();
        k_edge_msg<<<EDGE_GRID, 256>>>(ea, We + l * DIM, be + l * DIM);
        // h = relu((x + aggr) @ Wl1 + bl1)
        k_gemm128<<<GEMM_GRID, 128, GEMM_SMEM>>>(0, 2, Wl1 + l * DIM * DIM,
                                                 bl1 + l * DIM, 1, 1, N_NODES);
        // x = relu(h @ Wl2 + bl2)
        k_gemm128<<<GEMM_GRID, 128, GEMM_SMEM>>>(1, -1, Wl2 + l * DIM * DIM,
                                                 bl2 + l * DIM, 0, 1, N_NODES);
    }

    // A = x @ Wp1[0:128]  (into g_h),  B = x @ Wp1[128:256] (into g_B)
    k_gemm128<<<GEMM_GRID, 128, GEMM_SMEM>>>(0, -1, Wp1, nullptr, 1, 0, N_NODES);
    k_gemm128<<<GEMM_GRID, 128, GEMM_SMEM>>>(0, -1, Wp1 + DIM * DIM, nullptr, 3, 0, N_NODES);

    k_edge_pred<<<EDGE_GRID, 256>>>(bp1, Wp2, bp2, out);
}

// round 4
// speedup vs baseline: 1.1760x; 1.1760x over previous
#include <cuda_runtime.h>
#include <cstdint>

#define N_NODES 50000
#define N_EDGES 800000
#define DIM     128
#define SCAN_NB 196   // 196*256 = 50176 >= N_NODES

// ---------------- scratch (device globals; no allocation allowed) ----------------
__device__ float g_xbuf[N_NODES * DIM];   // current node features
__device__ float g_h   [N_NODES * DIM];   // hidden / predictor A
__device__ float g_aggr[N_NODES * DIM];   // x + message aggregation
__device__ float g_B   [N_NODES * DIM];   // predictor B
__device__ int   g_src [N_EDGES];
__device__ int   g_dst [N_EDGES];
__device__ int   g_ssrc[N_EDGES];         // src sorted by dst
__device__ float g_sea [N_EDGES];         // edge_attr sorted by dst
__device__ int   g_deg [N_NODES];
__device__ int   g_row [N_NODES + 1];
__device__ int   g_cur [N_NODES];
__device__ int   g_bsum[SCAN_NB];
__device__ int   g_is64;

__device__ __forceinline__ float* bufptr(int id) {
    switch (id) {
        case 0:  return g_xbuf;
        case 1:  return g_h;
        case 2:  return g_aggr;
        default: return g_B;
    }
}

// ---------------- packed f32x2 helpers (Blackwell) ----------------
__device__ __forceinline__ unsigned long long pack2b(float a) {
    unsigned long long r;
    asm("mov.b64 %0, {%1, %1};" : "=l"(r) : "f"(a));
    return r;
}
__device__ __forceinline__ unsigned long long fma2(unsigned long long a,
                                                   unsigned long long b,
                                                   unsigned long long c) {
    unsigned long long d;
    asm("fma.rn.f32x2 %0, %1, %2, %3;" : "=l"(d) : "l"(a), "l"(b), "l"(c));
    return d;
}

// ---------------- dtype detect + index normalize ----------------
__global__ void k_detect(const void* ei) {
    __shared__ int s;
    if (threadIdx.x == 0) s = 0;
    __syncthreads();
    const unsigned* w = (const unsigned*)ei;
    if (w[2 * threadIdx.x + 1] != 0u) atomicOr(&s, 1);
    __syncthreads();
    if (threadIdx.x == 0) g_is64 = (s == 0) ? 1 : 0;
}

__global__ void k_convert(const void* ei) {
    int i = blockIdx.x * blockDim.x + threadIdx.x;
    if (i >= N_EDGES) return;
    if (g_is64) {
        const long long* p = (const long long*)ei;
        g_src[i] = (int)p[i];
        g_dst[i] = (int)p[N_EDGES + i];
    } else {
        const int* p = (const int*)ei;
        g_src[i] = p[i];
        g_dst[i] = p[N_EDGES + i];
    }
}

// ---------------- CSR build ----------------
__global__ void k_zero_deg() {
    int i = blockIdx.x * blockDim.x + threadIdx.x;
    if (i < N_NODES) g_deg[i] = 0;
}

__global__ void k_hist() {
    int i = blockIdx.x * blockDim.x + threadIdx.x;
    if (i < N_EDGES) atomicAdd(&g_deg[g_dst[i]], 1);
}

// block-wise exclusive scan of degrees (256/block)
__global__ void k_scanA() {
    __shared__ int s[256];
    int t = threadIdx.x;
    int idx = blockIdx.x * 256 + t;
    int v = (idx < N_NODES) ? g_deg[idx] : 0;
    s[t] = v;
    __syncthreads();
    #pragma unroll
    for (int off = 1; off < 256; off <<= 1) {
        int add = (t >= off) ? s[t - off] : 0;
        __syncthreads();
        s[t] += add;
        __syncthreads();
    }
    int incl = s[t];
    if (idx < N_NODES) g_row[idx] = incl - v;
    if (t == 255) g_bsum[blockIdx.x] = incl;
}

__global__ void k_scanB() {
    __shared__ int s[256];
    int t = threadIdx.x;
    int v = (t < SCAN_NB) ? g_bsum[t] : 0;
    s[t] = v;
    __syncthreads();
    #pragma unroll
    for (int off = 1; off < 256; off <<= 1) {
        int add = (t >= off) ? s[t - off] : 0;
        __syncthreads();
        s[t] += add;
        __syncthreads();
    }
    if (t < SCAN_NB) g_bsum[t] = s[t] - v;  // exclusive
}

__global__ void k_scanC() {
    int idx = blockIdx.x * 256 + threadIdx.x;
    if (idx < N_NODES) {
        int r = g_row[idx] + g_bsum[blockIdx.x];
        g_row[idx] = r;
        g_cur[idx] = r;
    }
    if (idx == 0) g_row[N_NODES] = N_EDGES;
}

__global__ void k_scatter(const float* __restrict__ ea) {
    int e = blockIdx.x * blockDim.x + threadIdx.x;
    if (e >= N_EDGES) return;
    int d = g_dst[e];
    int pos = atomicAdd(&g_cur[d], 1);
    g_ssrc[pos] = g_src[e];
    g_sea[pos]  = ea[e];
}

// ---------------- CSR aggregation ----------------
// aggr[n] = x[n] + sum_{e in CSR row n} relu(x[src_e] + a_e*We + be)
// one warp per node, register accumulation, plain store; xext!=null only for layer 0
__global__ void __launch_bounds__(256)
k_aggr(const float* __restrict__ xext,
       const float* __restrict__ We, const float* __restrict__ be) {
    int gt   = blockIdx.x * blockDim.x + threadIdx.x;
    int node = gt >> 5;
    int lane = gt & 31;
    if (node >= N_NODES) return;

    const float* xin = xext ? xext : g_xbuf;

    float4 wv = ((const float4*)We)[lane];
    float4 bv = ((const float4*)be)[lane];
    const float4* xv = (const float4*)xin;

    float4 acc = xv[(size_t)node * 32 + lane];   // (1+eps)*x, eps=0
    int j   = g_row[node];
    int end = g_row[node + 1];

    for (; j + 1 < end; j += 2) {
        int   s0 = __ldg(g_ssrc + j),     s1 = __ldg(g_ssrc + j + 1);
        float a0 = __ldg(g_sea + j),      a1 = __ldg(g_sea + j + 1);
        float4 x0 = xv[(size_t)s0 * 32 + lane];
        float4 x1 = xv[(size_t)s1 * 32 + lane];
        acc.x += fmaxf(x0.x + fmaf(a0, wv.x, bv.x), 0.f)
               + fmaxf(x1.x + fmaf(a1, wv.x, bv.x), 0.f);
        acc.y += fmaxf(x0.y + fmaf(a0, wv.y, bv.y), 0.f)
               + fmaxf(x1.y + fmaf(a1, wv.y, bv.y), 0.f);
        acc.z += fmaxf(x0.z + fmaf(a0, wv.z, bv.z), 0.f)
               + fmaxf(x1.z + fmaf(a1, wv.z, bv.z), 0.f);
        acc.w += fmaxf(x0.w + fmaf(a0, wv.w, bv.w), 0.f)
               + fmaxf(x1.w + fmaf(a1, wv.w, bv.w), 0.f);
    }
    if (j < end) {
        int   s0 = __ldg(g_ssrc + j);
        float a0 = __ldg(g_sea + j);
        float4 x0 = xv[(size_t)s0 * 32 + lane];
        acc.x += fmaxf(x0.x + fmaf(a0, wv.x, bv.x), 0.f);
        acc.y += fmaxf(x0.y + fmaf(a0, wv.y, bv.y), 0.f);
        acc.z += fmaxf(x0.z + fmaf(a0, wv.z, bv.z), 0.f);
        acc.w += fmaxf(x0.w + fmaf(a0, wv.w, bv.w), 0.f);
    }
    ((float4*)g_aggr)[(size_t)node * 32 + lane] = acc;
}

// ---------------- 128x128 GEMM, thread-per-row, W in smem, f32x2 packed ----------------
// out[row] = act( A[row] @ W + bias ), buffers by id
__global__ void __launch_bounds__(128)
k_gemm128(int ia, const float* __restrict__ W,
          const float* __restrict__ bias, int io, int relu, int nrows) {
    extern __shared__ float sW[];  // 64 KB
    const float4* Wv  = (const float4*)W;
    float4*       sWv = (float4*)sW;
    #pragma unroll
    for (int i = 0; i < 32; i++)
        sWv[i * 128 + threadIdx.x] = Wv[i * 128 + threadIdx.x];
    __syncthreads();

    int row = blockIdx.x * 128 + threadIdx.x;
    if (row >= nrows) return;

    const float* A   = bufptr(ia);
    float*       out = bufptr(io);

    float in[DIM];
    {
        const float4* a4 = (const float4*)(A + (size_t)row * DIM);
        #pragma unroll
        for (int k4 = 0; k4 < 32; k4++) {
            float4 v = a4[k4];
            in[4 * k4 + 0] = v.x; in[4 * k4 + 1] = v.y;
            in[4 * k4 + 2] = v.z; in[4 * k4 + 3] = v.w;
        }
    }

    float2* o2 = (float2*)(out + (size_t)row * DIM);
    #pragma unroll 1
    for (int j0 = 0; j0 < DIM; j0 += 16) {
        unsigned long long acc[8];
        if (bias) {
            const unsigned long long* b2 = (const unsigned long long*)(bias + j0);
            #pragma unroll
            for (int i = 0; i < 8; i++) acc[i] = b2[i];
        } else {
            #pragma unroll
            for (int i = 0; i < 8; i++) acc[i] = 0ull;
        }
        #pragma unroll
        for (int k = 0; k < DIM; k++) {
            unsigned long long a2 = pack2b(in[k]);
            const ulonglong2* wp = (const ulonglong2*)(sW + k * DIM + j0);
            ulonglong2 w0 = wp[0], w1 = wp[1], w2 = wp[2], w3 = wp[3];
            acc[0] = fma2(a2, w0.x, acc[0]);
            acc[1] = fma2(a2, w0.y, acc[1]);
            acc[2] = fma2(a2, w1.x, acc[2]);
            acc[3] = fma2(a2, w1.y, acc[3]);
            acc[4] = fma2(a2, w2.x, acc[4]);
            acc[5] = fma2(a2, w2.y, acc[5]);
            acc[6] = fma2(a2, w3.x, acc[6]);
            acc[7] = fma2(a2, w3.y, acc[7]);
        }
        #pragma unroll
        for (int i = 0; i < 8; i++) {
            float2 v = *(float2*)&acc[i];
            if (relu) { v.x = fmaxf(v.x, 0.f); v.y = fmaxf(v.y, 0.f); }
            o2[j0 / 2 + i] = v;
        }
    }
}

// ---------------- edge predictor epilogue ----------------
// out[e] = relu(A[src] + B[dst] + bp1) . Wp2 + bp2   (1 warp/edge)
__global__ void k_edge_pred(const float* __restrict__ bp1,
                            const float* __restrict__ Wp2,
                            const float* __restrict__ bp2,
                            float* __restrict__ out) {
    int gt   = blockIdx.x * blockDim.x + threadIdx.x;
    int warp = gt >> 5;
    int lane = gt & 31;
    int nw   = (gridDim.x * blockDim.x) >> 5;

    float4 b1 = ((const float4*)bp1)[lane];
    float4 w2 = ((const float4*)Wp2)[lane];
    float  b2 = __ldg(bp2);

    for (int e = warp; e < N_EDGES; e += nw) {
        int s = g_src[e];
        int d = g_dst[e];
        float4 av = ((const float4*)(g_h + (size_t)s * DIM))[lane];
        float4 bv = ((const float4*)(g_B + (size_t)d * DIM))[lane];
        float p = 0.f;
        p = fmaf(fmaxf(av.x + bv.x + b1.x, 0.f), w2.x, p);
        p = fmaf(fmaxf(av.y + bv.y + b1.y, 0.f), w2.y, p);
        p = fmaf(fmaxf(av.z + bv.z + b1.z, 0.f), w2.z, p);
        p = fmaf(fmaxf(av.w + bv.w + b1.w, 0.f), w2.w, p);
        #pragma unroll
        for (int o = 16; o > 0; o >>= 1)
            p += __shfl_xor_sync(0xffffffffu, p, o);
        if (lane == 0) out[e] = p + b2;
    }
}

// ---------------- launch ----------------
extern "C" void kernel_launch(void* const* d_in, const int* in_sizes, int n_in,
                              void* d_out, int out_size) {
    const float* x   = (const float*)d_in[0];
    const float* ea  = (const float*)d_in[1];
    const void*  ei  = d_in[2];
    const float* Wl1 = (const float*)d_in[3];
    const float* bl1 = (const float*)d_in[4];
    const float* Wl2 = (const float*)d_in[5];
    const float* bl2 = (const float*)d_in[6];
    const float* We  = (const float*)d_in[7];
    const float* be  = (const float*)d_in[8];
    const float* Wp1 = (const float*)d_in[9];
    const float* bp1 = (const float*)d_in[10];
    const float* Wp2 = (const float*)d_in[11];
    const float* bp2 = (const float*)d_in[12];
    float* out = (float*)d_out;

    cudaFuncSetAttribute(k_gemm128, cudaFuncAttributeMaxDynamicSharedMemorySize,
                         DIM * DIM * (int)sizeof(float));

    const int GEMM_SMEM = DIM * DIM * (int)sizeof(float);
    const int GEMM_GRID = (N_NODES + 127) / 128;         // 391
    const int EDGE_GRID = (N_EDGES + 255) / 256;         // 3125
    const int NODE_GRID = (N_NODES + 255) / 256;         // 196
    const int AGGR_GRID = (N_NODES * 32 + 255) / 256;    // 6250

    // index normalize + CSR build (once per call)
    k_detect<<<1, 64>>>(ei);
    k_convert<<<EDGE_GRID, 256>>>(ei);
    k_zero_deg<<<NODE_GRID, 256>>>();
    k_hist<<<EDGE_GRID, 256>>>();
    k_scanA<<<SCAN_NB, 256>>>();
    k_scanB<<<1, 256>>>();
    k_scanC<<<SCAN_NB, 256>>>();
    k_scatter<<<EDGE_GRID, 256>>>(ea);

    for (int l = 0; l < 3; l++) {
        // aggr = x + sum(msg);  layer 0 reads the external x directly
        k_aggr<<<AGGR_GRID, 256>>>((l == 0) ? x : nullptr,
                                   We + l * DIM, be + l * DIM);
        // h = relu(aggr @ Wl1 + bl1)
        k_gemm128<<<GEMM_GRID, 128, GEMM_SMEM>>>(2, Wl1 + l * DIM * DIM,
                                                 bl1 + l * DIM, 1, 1, N_NODES);
        // x = relu(h @ Wl2 + bl2)
        k_gemm128<<<GEMM_GRID, 128, GEMM_SMEM>>>(1, Wl2 + l * DIM * DIM,
                                                 bl2 + l * DIM, 0, 1, N_NODES);
    }

    // A = x @ Wp1[0:128] (g_h),  B = x @ Wp1[128:256] (g_B)
    k_gemm128<<<GEMM_GRID, 128, GEMM_SMEM>>>(0, Wp1, nullptr, 1, 0, N_NODES);
    k_gemm128<<<GEMM_GRID, 128, GEMM_SMEM>>>(0, Wp1 + DIM * DIM, nullptr, 3, 0, N_NODES);

    k_edge_pred<<<1184, 256>>>(bp1, Wp2, bp2, out);
}

// round 5
// speedup vs baseline: 1.7056x; 1.4503x over previous
#include <cuda_runtime.h>
#include <cstdint>

#define N_NODES 50000
#define N_EDGES 800000
#define DIM     128
#define SCAN_NB 196   // 196*256 = 50176 >= N_NODES
#define WPITCH  136   // padded smem pitch for W (conflict-free B frag loads)

// ---------------- scratch (device globals; no allocation allowed) ----------------
__device__ float g_xbuf[N_NODES * DIM];   // current node features
__device__ float g_h   [N_NODES * DIM];   // hidden / predictor A
__device__ float g_aggr[N_NODES * DIM];   // x + message aggregation
__device__ float g_B   [N_NODES * DIM];   // predictor B
__device__ int   g_src [N_EDGES];
__device__ int   g_dst [N_EDGES];
__device__ int   g_ssrc[N_EDGES];         // src sorted by dst
__device__ float g_sea [N_EDGES];         // edge_attr sorted by dst
__device__ int   g_deg [N_NODES];
__device__ int   g_row [N_NODES + 1];
__device__ int   g_cur [N_NODES];
__device__ int   g_bsum[SCAN_NB];
__device__ int   g_is64;

__device__ __forceinline__ float* bufptr(int id) {
    switch (id) {
        case 0:  return g_xbuf;
        case 1:  return g_h;
        case 2:  return g_aggr;
        default: return g_B;
    }
}

// ---------------- tf32 helpers ----------------
__device__ __forceinline__ uint32_t f2tf(float x) {
    uint32_t u;
    asm("cvt.rna.tf32.f32 %0, %1;" : "=r"(u) : "f"(x));
    return u;
}
__device__ __forceinline__ void mma_tf32(float* c, const uint32_t* a,
                                         const uint32_t* b) {
    asm("mma.sync.aligned.m16n8k8.row.col.f32.tf32.tf32.f32 "
        "{%0,%1,%2,%3},{%4,%5,%6,%7},{%8,%9},{%0,%1,%2,%3};"
        : "+f"(c[0]), "+f"(c[1]), "+f"(c[2]), "+f"(c[3])
        : "r"(a[0]), "r"(a[1]), "r"(a[2]), "r"(a[3]), "r"(b[0]), "r"(b[1]));
}

// ---------------- dtype detect + index normalize ----------------
__global__ void k_detect(const void* ei) {
    __shared__ int s;
    if (threadIdx.x == 0) s = 0;
    __syncthreads();
    const unsigned* w = (const unsigned*)ei;
    if (w[2 * threadIdx.x + 1] != 0u) atomicOr(&s, 1);
    __syncthreads();
    if (threadIdx.x == 0) g_is64 = (s == 0) ? 1 : 0;
}

__global__ void k_convert(const void* ei) {
    int i = blockIdx.x * blockDim.x + threadIdx.x;
    if (i >= N_EDGES) return;
    if (g_is64) {
        const long long* p = (const long long*)ei;
        g_src[i] = (int)p[i];
        g_dst[i] = (int)p[N_EDGES + i];
    } else {
        const int* p = (const int*)ei;
        g_src[i] = p[i];
        g_dst[i] = p[N_EDGES + i];
    }
}

// ---------------- CSR build ----------------
__global__ void k_zero_deg() {
    int i = blockIdx.x * blockDim.x + threadIdx.x;
    if (i < N_NODES) g_deg[i] = 0;
}

__global__ void k_hist() {
    int i = blockIdx.x * blockDim.x + threadIdx.x;
    if (i < N_EDGES) atomicAdd(&g_deg[g_dst[i]], 1);
}

__global__ void k_scanA() {
    __shared__ int s[256];
    int t = threadIdx.x;
    int idx = blockIdx.x * 256 + t;
    int v = (idx < N_NODES) ? g_deg[idx] : 0;
    s[t] = v;
    __syncthreads();
    #pragma unroll
    for (int off = 1; off < 256; off <<= 1) {
        int add = (t >= off) ? s[t - off] : 0;
        __syncthreads();
        s[t] += add;
        __syncthreads();
    }
    int incl = s[t];
    if (idx < N_NODES) g_row[idx] = incl - v;
    if (t == 255) g_bsum[blockIdx.x] = incl;
}

__global__ void k_scanB() {
    __shared__ int s[256];
    int t = threadIdx.x;
    int v = (t < SCAN_NB) ? g_bsum[t] : 0;
    s[t] = v;
    __syncthreads();
    #pragma unroll
    for (int off = 1; off < 256; off <<= 1) {
        int add = (t >= off) ? s[t - off] : 0;
        __syncthreads();
        s[t] += add;
        __syncthreads();
    }
    if (t < SCAN_NB) g_bsum[t] = s[t] - v;  // exclusive
}

__global__ void k_scanC() {
    int idx = blockIdx.x * 256 + threadIdx.x;
    if (idx < N_NODES) {
        int r = g_row[idx] + g_bsum[blockIdx.x];
        g_row[idx] = r;
        g_cur[idx] = r;
    }
    if (idx == 0) g_row[N_NODES] = N_EDGES;
}

__global__ void k_scatter(const float* __restrict__ ea) {
    int e = blockIdx.x * blockDim.x + threadIdx.x;
    if (e >= N_EDGES) return;
    int d = g_dst[e];
    int pos = atomicAdd(&g_cur[d], 1);
    g_ssrc[pos] = g_src[e];
    g_sea[pos]  = ea[e];
}

// ---------------- CSR aggregation ----------------
// aggr[n] = x[n] + sum_{e in row n} relu(x[src_e] + a_e*We + be); warp per node
__global__ void __launch_bounds__(256)
k_aggr(const float* __restrict__ xext,
       const float* __restrict__ We, const float* __restrict__ be) {
    int gt   = blockIdx.x * blockDim.x + threadIdx.x;
    int node = gt >> 5;
    int lane = gt & 31;
    if (node >= N_NODES) return;

    const float* xin = xext ? xext : g_xbuf;

    float4 wv = ((const float4*)We)[lane];
    float4 bv = ((const float4*)be)[lane];
    const float4* xv = (const float4*)xin;

    float4 acc = xv[(size_t)node * 32 + lane];   // (1+eps)*x, eps=0
    int j   = g_row[node];
    int end = g_row[node + 1];

    for (; j + 1 < end; j += 2) {
        int   s0 = __ldg(g_ssrc + j),     s1 = __ldg(g_ssrc + j + 1);
        float a0 = __ldg(g_sea + j),      a1 = __ldg(g_sea + j + 1);
        float4 x0 = xv[(size_t)s0 * 32 + lane];
        float4 x1 = xv[(size_t)s1 * 32 + lane];
        acc.x += fmaxf(x0.x + fmaf(a0, wv.x, bv.x), 0.f)
               + fmaxf(x1.x + fmaf(a1, wv.x, bv.x), 0.f);
        acc.y += fmaxf(x0.y + fmaf(a0, wv.y, bv.y), 0.f)
               + fmaxf(x1.y + fmaf(a1, wv.y, bv.y), 0.f);
        acc.z += fmaxf(x0.z + fmaf(a0, wv.z, bv.z), 0.f)
               + fmaxf(x1.z + fmaf(a1, wv.z, bv.z), 0.f);
        acc.w += fmaxf(x0.w + fmaf(a0, wv.w, bv.w), 0.f)
               + fmaxf(x1.w + fmaf(a1, wv.w, bv.w), 0.f);
    }
    if (j < end) {
        int   s0 = __ldg(g_ssrc + j);
        float a0 = __ldg(g_sea + j);
        float4 x0 = xv[(size_t)s0 * 32 + lane];
        acc.x += fmaxf(x0.x + fmaf(a0, wv.x, bv.x), 0.f);
        acc.y += fmaxf(x0.y + fmaf(a0, wv.y, bv.y), 0.f);
        acc.z += fmaxf(x0.z + fmaf(a0, wv.z, bv.z), 0.f);
        acc.w += fmaxf(x0.w + fmaf(a0, wv.w, bv.w), 0.f);
    }
    ((float4*)g_aggr)[(size_t)node * 32 + lane] = acc;
}

// ---------------- tensor-core GEMM: out = act(A @ W + bias), 3xTF32 ----------------
// block: 128 rows x 128 cols, 256 threads (8 warps), warp tile 32x64
__global__ void __launch_bounds__(256, 2)
k_gemm_tc(int ia, const float* __restrict__ W,
          const float* __restrict__ bias, int io, int relu, int nrows) {
    extern __shared__ float sW[];  // 128 * WPITCH floats
    {
        const float4* Wv = (const float4*)W;
        for (int i = threadIdx.x; i < 128 * 32; i += 256) {
            int r = i >> 5, c = i & 31;
            *(float4*)&sW[r * WPITCH + c * 4] = Wv[i];
        }
    }
    __syncthreads();

    const float* A   = bufptr(ia);
    float*       out = bufptr(io);

    int warp = threadIdx.x >> 5, lane = threadIdx.x & 31;
    int g   = lane >> 2;    // 0..7
    int tid = lane & 3;     // 0..3
    int mbase = blockIdx.x * 128 + (warp >> 1) * 32;
    int nbase = (warp & 1) * 64;

    float acc[2][8][4];
    #pragma unroll
    for (int mt = 0; mt < 2; mt++)
        #pragma unroll
        for (int nt = 0; nt < 8; nt++)
            #pragma unroll
            for (int i = 0; i < 4; i++) acc[mt][nt][i] = 0.f;

    int r0[2], r1[2];
    #pragma unroll
    for (int mt = 0; mt < 2; mt++) {
        int a = mbase + mt * 16 + g;
        r0[mt] = min(a, nrows - 1);
        r1[mt] = min(a + 8, nrows - 1);
    }

    #pragma unroll 1
    for (int k0 = 0; k0 < 128; k0 += 8) {
        // A fragments (hi/lo), loaded from global (L1/L2-resident tile)
        uint32_t ah[2][4], al[2][4];
        #pragma unroll
        for (int mt = 0; mt < 2; mt++) {
            float v0 = __ldg(A + (size_t)r0[mt] * DIM + k0 + tid);
            float v1 = __ldg(A + (size_t)r1[mt] * DIM + k0 + tid);
            float v2 = __ldg(A + (size_t)r0[mt] * DIM + k0 + tid + 4);
            float v3 = __ldg(A + (size_t)r1[mt] * DIM + k0 + tid + 4);
            ah[mt][0] = f2tf(v0); al[mt][0] = f2tf(v0 - __uint_as_float(ah[mt][0]));
            ah[mt][1] = f2tf(v1); al[mt][1] = f2tf(v1 - __uint_as_float(ah[mt][1]));
            ah[mt][2] = f2tf(v2); al[mt][2] = f2tf(v2 - __uint_as_float(ah[mt][2]));
            ah[mt][3] = f2tf(v3); al[mt][3] = f2tf(v3 - __uint_as_float(ah[mt][3]));
        }
        // B fragments in two halves of 4 n-tiles to limit registers
        #pragma unroll
        for (int nh = 0; nh < 2; nh++) {
            uint32_t bh[4][2], bl[4][2];
            #pragma unroll
            for (int q = 0; q < 4; q++) {
                int col = nbase + (nh * 4 + q) * 8 + g;
                float b0f = sW[(k0 + tid) * WPITCH + col];
                float b1f = sW[(k0 + tid + 4) * WPITCH + col];
                bh[q][0] = f2tf(b0f); bl[q][0] = f2tf(b0f - __uint_as_float(bh[q][0]));
                bh[q][1] = f2tf(b1f); bl[q][1] = f2tf(b1f - __uint_as_float(bh[q][1]));
            }
            #pragma unroll
            for (int mt = 0; mt < 2; mt++)
                #pragma unroll
                for (int q = 0; q < 4; q++) {
                    float* c = acc[mt][nh * 4 + q];
                    mma_tf32(c, al[mt], bh[q]);   // Al*Wh
                    mma_tf32(c, ah[mt], bl[q]);   // Ah*Wl
                    mma_tf32(c, ah[mt], bh[q]);   // Ah*Wh
                }
        }
    }

    // epilogue: bias + relu + store (c0,c1 adjacent cols -> float2)
    #pragma unroll
    for (int mt = 0; mt < 2; mt++) {
        int ra = mbase + mt * 16 + g;
        int rb = ra + 8;
        #pragma unroll
        for (int nt = 0; nt < 8; nt++) {
            int c = nbase + nt * 8 + tid * 2;
            float b0 = bias ? __ldg(bias + c)     : 0.f;
            float b1 = bias ? __ldg(bias + c + 1) : 0.f;
            float v0 = acc[mt][nt][0] + b0, v1 = acc[mt][nt][1] + b1;
            float v2 = acc[mt][nt][2] + b0, v3 = acc[mt][nt][3] + b1;
            if (relu) {
                v0 = fmaxf(v0, 0.f); v1 = fmaxf(v1, 0.f);
                v2 = fmaxf(v2, 0.f); v3 = fmaxf(v3, 0.f);
            }
            if (ra < nrows) *(float2*)&out[(size_t)ra * DIM + c] = make_float2(v0, v1);
            if (rb < nrows) *(float2*)&out[(size_t)rb * DIM + c] = make_float2(v2, v3);
        }
    }
}

// ---------------- edge predictor epilogue ----------------
// out[e] = relu(A[src] + B[dst] + bp1) . Wp2 + bp2   (1 warp/edge)
__global__ void k_edge_pred(const float* __restrict__ bp1,
                            const float* __restrict__ Wp2,
                            const float* __restrict__ bp2,
                            float* __restrict__ out) {
    int gt   = blockIdx.x * blockDim.x + threadIdx.x;
    int warp = gt >> 5;
    int lane = gt & 31;
    int nw   = (gridDim.x * blockDim.x) >> 5;

    float4 b1 = ((const float4*)bp1)[lane];
    float4 w2 = ((const float4*)Wp2)[lane];
    float  b2 = __ldg(bp2);

    for (int e = warp; e < N_EDGES; e += nw) {
        int s = g_src[e];
        int d = g_dst[e];
        float4 av = ((const float4*)(g_h + (size_t)s * DIM))[lane];
        float4 bv = ((const float4*)(g_B + (size_t)d * DIM))[lane];
        float p = 0.f;
        p = fmaf(fmaxf(av.x + bv.x + b1.x, 0.f), w2.x, p);
        p = fmaf(fmaxf(av.y + bv.y + b1.y, 0.f), w2.y, p);
        p = fmaf(fmaxf(av.z + bv.z + b1.z, 0.f), w2.z, p);
        p = fmaf(fmaxf(av.w + bv.w + b1.w, 0.f), w2.w, p);
        #pragma unroll
        for (int o = 16; o > 0; o >>= 1)
            p += __shfl_xor_sync(0xffffffffu, p, o);
        if (lane == 0) out[e] = p + b2;
    }
}

// ---------------- launch ----------------
extern "C" void kernel_launch(void* const* d_in, const int* in_sizes, int n_in,
                              void* d_out, int out_size) {
    const float* x   = (const float*)d_in[0];
    const float* ea  = (const float*)d_in[1];
    const void*  ei  = d_in[2];
    const float* Wl1 = (const float*)d_in[3];
    const float* bl1 = (const float*)d_in[4];
    const float* Wl2 = (const float*)d_in[5];
    const float* bl2 = (const float*)d_in[6];
    const float* We  = (const float*)d_in[7];
    const float* be  = (const float*)d_in[8];
    const float* Wp1 = (const float*)d_in[9];
    const float* bp1 = (const float*)d_in[10];
    const float* Wp2 = (const float*)d_in[11];
    const float* bp2 = (const float*)d_in[12];
    float* out = (float*)d_out;

    const int GEMM_SMEM = 128 * WPITCH * (int)sizeof(float);  // 69632
    cudaFuncSetAttribute(k_gemm_tc, cudaFuncAttributeMaxDynamicSharedMemorySize,
                         GEMM_SMEM);

    const int GEMM_GRID = (N_NODES + 127) / 128;         // 391
    const int EDGE_GRID = (N_EDGES + 255) / 256;         // 3125
    const int NODE_GRID = (N_NODES + 255) / 256;         // 196
    const int AGGR_GRID = (N_NODES * 32 + 255) / 256;    // 6250

    // index normalize + CSR build (once per call)
    k_detect<<<1, 64>>>(ei);
    k_convert<<<EDGE_GRID, 256>>>(ei);
    k_zero_deg<<<NODE_GRID, 256>>>();
    k_hist<<<EDGE_GRID, 256>>>();
    k_scanA<<<SCAN_NB, 256>>>();
    k_scanB<<<1, 256>>>();
    k_scanC<<<SCAN_NB, 256>>>();
    k_scatter<<<EDGE_GRID, 256>>>(ea);

    for (int l = 0; l < 3; l++) {
        // aggr = x + sum(msg);  layer 0 reads the external x directly
        k_aggr<<<AGGR_GRID, 256>>>((l == 0) ? x : nullptr,
                                   We + l * DIM, be + l * DIM);
        // h = relu(aggr @ Wl1 + bl1)
        k_gemm_tc<<<GEMM_GRID, 256, GEMM_SMEM>>>(2, Wl1 + l * DIM * DIM,
                                                 bl1 + l * DIM, 1, 1, N_NODES);
        // x = relu(h @ Wl2 + bl2)
        k_gemm_tc<<<GEMM_GRID, 256, GEMM_SMEM>>>(1, Wl2 + l * DIM * DIM,
                                                 bl2 + l * DIM, 0, 1, N_NODES);
    }

    // A = x @ Wp1[0:128] (g_h),  B = x @ Wp1[128:256] (g_B)
    k_gemm_tc<<<GEMM_GRID, 256, GEMM_SMEM>>>(0, Wp1, nullptr, 1, 0, N_NODES);
    k_gemm_tc<<<GEMM_GRID, 256, GEMM_SMEM>>>(0, Wp1 + DIM * DIM, nullptr, 3, 0, N_NODES);

    k_edge_pred<<<1184, 256>>>(bp1, Wp2, bp2, out);
}

// round 6
// speedup vs baseline: 2.2454x; 1.3165x over previous
#include <cuda_runtime.h>
#include <cstdint>

#define N_NODES 50000
#define N_EDGES 800000
#define DIM     128
#define SCAN_NB 196   // 196*256 = 50176 >= N_NODES
#define BPITCH  136   // u32 pitch for packed-bf16x2 W planes (conflict-free)

// ---------------- scratch (device globals; no allocation allowed) ----------------
__device__ float g_xbuf[N_NODES * DIM];   // current node features
__device__ float g_h   [N_NODES * DIM];   // hidden / predictor A
__device__ float g_aggr[N_NODES * DIM];   // x + message aggregation
__device__ float g_B   [N_NODES * DIM];   // predictor B
__device__ int   g_src [N_EDGES];
__device__ int   g_dst [N_EDGES];
__device__ int   g_ssrc[N_EDGES];         // src sorted by dst
__device__ float g_sea [N_EDGES];         // edge_attr sorted by dst
__device__ int   g_deg [N_NODES];
__device__ int   g_row [N_NODES + 1];
__device__ int   g_cur [N_NODES];
__device__ int   g_bsum[SCAN_NB];
__device__ int   g_is64;

__device__ __forceinline__ float* bufptr(int id) {
    switch (id) {
        case 0:  return g_xbuf;
        case 1:  return g_h;
        case 2:  return g_aggr;
        default: return g_B;
    }
}

// ---------------- bf16 helpers ----------------
// pack: d.hi = bf16(vhi), d.lo = bf16(vlo)
__device__ __forceinline__ uint32_t packbf(float vhi, float vlo) {
    uint32_t r;
    asm("cvt.rn.bf16x2.f32 %0, %1, %2;" : "=r"(r) : "f"(vhi), "f"(vlo));
    return r;
}
__device__ __forceinline__ void mma_bf16(float* c, const uint32_t* a,
                                         const uint32_t* b) {
    asm("mma.sync.aligned.m16n8k16.row.col.f32.bf16.bf16.f32 "
        "{%0,%1,%2,%3},{%4,%5,%6,%7},{%8,%9},{%0,%1,%2,%3};"
        : "+f"(c[0]), "+f"(c[1]), "+f"(c[2]), "+f"(c[3])
        : "r"(a[0]), "r"(a[1]), "r"(a[2]), "r"(a[3]), "r"(b[0]), "r"(b[1]));
}
// split a float2 (v0 = lower k, v1 = upper k) into bf16x2 hi + residual-lo words
__device__ __forceinline__ void split2(float2 v, uint32_t& hi, uint32_t& lo) {
    hi = packbf(v.y, v.x);
    float h0 = __uint_as_float(hi << 16);
    float h1 = __uint_as_float(hi & 0xffff0000u);
    lo = packbf(v.y - h1, v.x - h0);
}

// ---------------- dtype detect + index normalize ----------------
__global__ void k_detect(const void* ei) {
    __shared__ int s;
    if (threadIdx.x == 0) s = 0;
    __syncthreads();
    const unsigned* w = (const unsigned*)ei;
    if (w[2 * threadIdx.x + 1] != 0u) atomicOr(&s, 1);
    __syncthreads();
    if (threadIdx.x == 0) g_is64 = (s == 0) ? 1 : 0;
}

__global__ void k_convert(const void* ei) {
    int i = blockIdx.x * blockDim.x + threadIdx.x;
    if (i >= N_EDGES) return;
    if (g_is64) {
        const long long* p = (const long long*)ei;
        g_src[i] = (int)p[i];
        g_dst[i] = (int)p[N_EDGES + i];
    } else {
        const int* p = (const int*)ei;
        g_src[i] = p[i];
        g_dst[i] = p[N_EDGES + i];
    }
}

// ---------------- CSR build ----------------
__global__ void k_zero_deg() {
    int i = blockIdx.x * blockDim.x + threadIdx.x;
    if (i < N_NODES) g_deg[i] = 0;
}

__global__ void k_hist() {
    int i = blockIdx.x * blockDim.x + threadIdx.x;
    if (i < N_EDGES) atomicAdd(&g_deg[g_dst[i]], 1);
}

__global__ void k_scanA() {
    __shared__ int s[256];
    int t = threadIdx.x;
    int idx = blockIdx.x * 256 + t;
    int v = (idx < N_NODES) ? g_deg[idx] : 0;
    s[t] = v;
    __syncthreads();
    #pragma unroll
    for (int off = 1; off < 256; off <<= 1) {
        int add = (t >= off) ? s[t - off] : 0;
        __syncthreads();
        s[t] += add;
        __syncthreads();
    }
    int incl = s[t];
    if (idx < N_NODES) g_row[idx] = incl - v;
    if (t == 255) g_bsum[blockIdx.x] = incl;
}

__global__ void k_scanB() {
    __shared__ int s[256];
    int t = threadIdx.x;
    int v = (t < SCAN_NB) ? g_bsum[t] : 0;
    s[t] = v;
    __syncthreads();
    #pragma unroll
    for (int off = 1; off < 256; off <<= 1) {
        int add = (t >= off) ? s[t - off] : 0;
        __syncthreads();
        s[t] += add;
        __syncthreads();
    }
    if (t < SCAN_NB) g_bsum[t] = s[t] - v;  // exclusive
}

__global__ void k_scanC() {
    int idx = blockIdx.x * 256 + threadIdx.x;
    if (idx < N_NODES) {
        int r = g_row[idx] + g_bsum[blockIdx.x];
        g_row[idx] = r;
        g_cur[idx] = r;
    }
    if (idx == 0) g_row[N_NODES] = N_EDGES;
}

__global__ void k_scatter(const float* __restrict__ ea) {
    int e = blockIdx.x * blockDim.x + threadIdx.x;
    if (e >= N_EDGES) return;
    int d = g_dst[e];
    int pos = atomicAdd(&g_cur[d], 1);
    g_ssrc[pos] = g_src[e];
    g_sea[pos]  = ea[e];
}

// ---------------- CSR aggregation ----------------
// aggr[n] = x[n] + sum_{e in row n} relu(x[src_e] + a_e*We + be); warp per node
__global__ void __launch_bounds__(256)
k_aggr(const float* __restrict__ xext,
       const float* __restrict__ We, const float* __restrict__ be) {
    int gt   = blockIdx.x * blockDim.x + threadIdx.x;
    int node = gt >> 5;
    int lane = gt & 31;
    if (node >= N_NODES) return;

    const float* xin = xext ? xext : g_xbuf;

    float4 wv = ((const float4*)We)[lane];
    float4 bv = ((const float4*)be)[lane];
    const float4* xv = (const float4*)xin;

    float4 acc = xv[(size_t)node * 32 + lane];   // (1+eps)*x, eps=0
    int j   = g_row[node];
    int end = g_row[node + 1];

    for (; j + 1 < end; j += 2) {
        int   s0 = __ldg(g_ssrc + j),     s1 = __ldg(g_ssrc + j + 1);
        float a0 = __ldg(g_sea + j),      a1 = __ldg(g_sea + j + 1);
        float4 x0 = xv[(size_t)s0 * 32 + lane];
        float4 x1 = xv[(size_t)s1 * 32 + lane];
        acc.x += fmaxf(x0.x + fmaf(a0, wv.x, bv.x), 0.f)
               + fmaxf(x1.x + fmaf(a1, wv.x, bv.x), 0.f);
        acc.y += fmaxf(x0.y + fmaf(a0, wv.y, bv.y), 0.f)
               + fmaxf(x1.y + fmaf(a1, wv.y, bv.y), 0.f);
        acc.z += fmaxf(x0.z + fmaf(a0, wv.z, bv.z), 0.f)
               + fmaxf(x1.z + fmaf(a1, wv.z, bv.z), 0.f);
        acc.w += fmaxf(x0.w + fmaf(a0, wv.w, bv.w), 0.f)
               + fmaxf(x1.w + fmaf(a1, wv.w, bv.w), 0.f);
    }
    if (j < end) {
        int   s0 = __ldg(g_ssrc + j);
        float a0 = __ldg(g_sea + j);
        float4 x0 = xv[(size_t)s0 * 32 + lane];
        acc.x += fmaxf(x0.x + fmaf(a0, wv.x, bv.x), 0.f);
        acc.y += fmaxf(x0.y + fmaf(a0, wv.y, bv.y), 0.f);
        acc.z += fmaxf(x0.z + fmaf(a0, wv.z, bv.z), 0.f);
        acc.w += fmaxf(x0.w + fmaf(a0, wv.w, bv.w), 0.f);
    }
    ((float4*)g_aggr)[(size_t)node * 32 + lane] = acc;
}

// ---------------- tensor-core GEMM: out = act(A @ W + bias), bf16x3 ----------------
// block: 128 rows x 128 cols, 256 threads (8 warps), warp tile 32x64
// W pre-split into packed-bf16x2 hi/lo planes in smem: plane[k/2][n], pitch BPITCH
__global__ void __launch_bounds__(256, 2)
k_gemm_tc(int ia, const float* __restrict__ W,
          const float* __restrict__ bias, int io, int relu, int nrows) {
    extern __shared__ uint32_t sWp[];          // 2 * 64 * BPITCH u32
    uint32_t* sHi = sWp;
    uint32_t* sLo = sWp + 64 * BPITCH;
    for (int i = threadIdx.x; i < 64 * 128; i += 256) {
        int k2 = i >> 7, n = i & 127;
        float v0 = __ldg(W + (2 * k2)     * DIM + n);
        float v1 = __ldg(W + (2 * k2 + 1) * DIM + n);
        uint32_t hi, lo;
        split2(make_float2(v0, v1), hi, lo);
        sHi[k2 * BPITCH + n] = hi;
        sLo[k2 * BPITCH + n] = lo;
    }
    __syncthreads();

    const float* A   = bufptr(ia);
    float*       out = bufptr(io);

    int warp = threadIdx.x >> 5, lane = threadIdx.x & 31;
    int g   = lane >> 2;    // 0..7
    int tid = lane & 3;     // 0..3
    int mbase = blockIdx.x * 128 + (warp >> 1) * 32;
    int nbase = (warp & 1) * 64;

    float acc[2][8][4];
    #pragma unroll
    for (int mt = 0; mt < 2; mt++)
        #pragma unroll
        for (int nt = 0; nt < 8; nt++)
            #pragma unroll
            for (int i = 0; i < 4; i++) acc[mt][nt][i] = 0.f;

    int r0[2], r1[2];
    #pragma unroll
    for (int mt = 0; mt < 2; mt++) {
        int a = mbase + mt * 16 + g;
        r0[mt] = min(a, nrows - 1);
        r1[mt] = min(a + 8, nrows - 1);
    }

    #pragma unroll 1
    for (int c0 = 0; c0 < 128; c0 += 16) {
        int kq = c0 + tid * 2;
        // A fragments: hi + residual-lo, packed bf16x2
        uint32_t ah[2][4], al[2][4];
        #pragma unroll
        for (int mt = 0; mt < 2; mt++) {
            float2 p00 = *(const float2*)(A + (size_t)r0[mt] * DIM + kq);
            float2 p10 = *(const float2*)(A + (size_t)r1[mt] * DIM + kq);
            float2 p01 = *(const float2*)(A + (size_t)r0[mt] * DIM + kq + 8);
            float2 p11 = *(const float2*)(A + (size_t)r1[mt] * DIM + kq + 8);
            split2(p00, ah[mt][0], al[mt][0]);
            split2(p10, ah[mt][1], al[mt][1]);
            split2(p01, ah[mt][2], al[mt][2]);
            split2(p11, ah[mt][3], al[mt][3]);
        }
        int kb = (c0 >> 1) + tid;   // word row in planes
        #pragma unroll
        for (int nh = 0; nh < 2; nh++) {
            uint32_t bh[4][2], bl[4][2];
            #pragma unroll
            for (int q = 0; q < 4; q++) {
                int col = nbase + (nh * 4 + q) * 8 + g;
                bh[q][0] = sHi[kb * BPITCH + col];
                bh[q][1] = sHi[(kb + 4) * BPITCH + col];
                bl[q][0] = sLo[kb * BPITCH + col];
                bl[q][1] = sLo[(kb + 4) * BPITCH + col];
            }
            #pragma unroll
            for (int mt = 0; mt < 2; mt++)
                #pragma unroll
                for (int q = 0; q < 4; q++) {
                    float* c = acc[mt][nh * 4 + q];
                    mma_bf16(c, al[mt], bh[q]);   // Al*Wh
                    mma_bf16(c, ah[mt], bl[q]);   // Ah*Wl
                    mma_bf16(c, ah[mt], bh[q]);   // Ah*Wh
                }
        }
    }

    // epilogue: bias + relu + store (c0,c1 adjacent cols -> float2)
    #pragma unroll
    for (int mt = 0; mt < 2; mt++) {
        int ra = mbase + mt * 16 + g;
        int rb = ra + 8;
        #pragma unroll
        for (int nt = 0; nt < 8; nt++) {
            int c = nbase + nt * 8 + tid * 2;
            float b0 = bias ? __ldg(bias + c)     : 0.f;
            float b1 = bias ? __ldg(bias + c + 1) : 0.f;
            float v0 = acc[mt][nt][0] + b0, v1 = acc[mt][nt][1] + b1;
            float v2 = acc[mt][nt][2] + b0, v3 = acc[mt][nt][3] + b1;
            if (relu) {
                v0 = fmaxf(v0, 0.f); v1 = fmaxf(v1, 0.f);
                v2 = fmaxf(v2, 0.f); v3 = fmaxf(v3, 0.f);
            }
            if (ra < nrows) *(float2*)&out[(size_t)ra * DIM + c] = make_float2(v0, v1);
            if (rb < nrows) *(float2*)&out[(size_t)rb * DIM + c] = make_float2(v2, v3);
        }
    }
}

// ---------------- edge predictor epilogue ----------------
// out[e] = relu(A[src] + B[dst] + bp1) . Wp2 + bp2   (1 warp/edge)
__global__ void k_edge_pred(const float* __restrict__ bp1,
                            const float* __restrict__ Wp2,
                            const float* __restrict__ bp2,
                            float* __restrict__ out) {
    int gt   = blockIdx.x * blockDim.x + threadIdx.x;
    int warp = gt >> 5;
    int lane = gt & 31;
    int nw   = (gridDim.x * blockDim.x) >> 5;

    float4 b1 = ((const float4*)bp1)[lane];
    float4 w2 = ((const float4*)Wp2)[lane];
    float  b2 = __ldg(bp2);

    for (int e = warp; e < N_EDGES; e += nw) {
        int s = g_src[e];
        int d = g_dst[e];
        float4 av = ((const float4*)(g_h + (size_t)s * DIM))[lane];
        float4 bv = ((const float4*)(g_B + (size_t)d * DIM))[lane];
        float p = 0.f;
        p = fmaf(fmaxf(av.x + bv.x + b1.x, 0.f), w2.x, p);
        p = fmaf(fmaxf(av.y + bv.y + b1.y, 0.f), w2.y, p);
        p = fmaf(fmaxf(av.z + bv.z + b1.z, 0.f), w2.z, p);
        p = fmaf(fmaxf(av.w + bv.w + b1.w, 0.f), w2.w, p);
        #pragma unroll
        for (int o = 16; o > 0; o >>= 1)
            p += __shfl_xor_sync(0xffffffffu, p, o);
        if (lane == 0) out[e] = p + b2;
    }
}

// ---------------- launch ----------------
extern "C" void kernel_launch(void* const* d_in, const int* in_sizes, int n_in,
                              void* d_out, int out_size) {
    const float* x   = (const float*)d_in[0];
    const float* ea  = (const float*)d_in[1];
    const void*  ei  = d_in[2];
    const float* Wl1 = (const float*)d_in[3];
    const float* bl1 = (const float*)d_in[4];
    const float* Wl2 = (const float*)d_in[5];
    const float* bl2 = (const float*)d_in[6];
    const float* We  = (const float*)d_in[7];
    const float* be  = (const float*)d_in[8];
    const float* Wp1 = (const float*)d_in[9];
    const float* bp1 = (const float*)d_in[10];
    const float* Wp2 = (const float*)d_in[11];
    const float* bp2 = (const float*)d_in[12];
    float* out = (float*)d_out;

    const int GEMM_SMEM = 2 * 64 * BPITCH * (int)sizeof(uint32_t);  // 69632
    cudaFuncSetAttribute(k_gemm_tc, cudaFuncAttributeMaxDynamicSharedMemorySize,
                         GEMM_SMEM);

    const int GEMM_GRID = (N_NODES + 127) / 128;         // 391
    const int EDGE_GRID = (N_EDGES + 255) / 256;         // 3125
    const int NODE_GRID = (N_NODES + 255) / 256;         // 196
    const int AGGR_GRID = (N_NODES * 32 + 255) / 256;    // 6250

    // index normalize + CSR build (once per call)
    k_detect<<<1, 64>>>(ei);
    k_convert<<<EDGE_GRID, 256>>>(ei);
    k_zero_deg<<<NODE_GRID, 256>>>();
    k_hist<<<EDGE_GRID, 256>>>();
    k_scanA<<<SCAN_NB, 256>>>();
    k_scanB<<<1, 256>>>();
    k_scanC<<<SCAN_NB, 256>>>();
    k_scatter<<<EDGE_GRID, 256>>>(ea);

    for (int l = 0; l < 3; l++) {
        // aggr = x + sum(msg);  layer 0 reads the external x directly
        k_aggr<<<AGGR_GRID, 256>>>((l == 0) ? x : nullptr,
                                   We + l * DIM, be + l * DIM);
        // h = relu(aggr @ Wl1 + bl1)
        k_gemm_tc<<<GEMM_GRID, 256, GEMM_SMEM>>>(2, Wl1 + l * DIM * DIM,
                                                 bl1 + l * DIM, 1, 1, N_NODES);
        // x = relu(h @ Wl2 + bl2)
        k_gemm_tc<<<GEMM_GRID, 256, GEMM_SMEM>>>(1, Wl2 + l * DIM * DIM,
                                                 bl2 + l * DIM, 0, 1, N_NODES);
    }

    // A = x @ Wp1[0:128] (g_h),  B = x @ Wp1[128:256] (g_B)
    k_gemm_tc<<<GEMM_GRID, 256, GEMM_SMEM>>>(0, Wp1, nullptr, 1, 0, N_NODES);
    k_gemm_tc<<<GEMM_GRID, 256, GEMM_SMEM>>>(0, Wp1 + DIM * DIM, nullptr, 3, 0, N_NODES);

    k_edge_pred<<<1184, 256>>>(bp1, Wp2, bp2, out);
}

// round 7
// speedup vs baseline: 2.3462x; 1.0449x over previous
#include <cuda_runtime.h>
#include <cstdint>

#define N_NODES 50000
#define N_EDGES 800000
#define DIM     128
#define SCAN_NB 196   // 196*256 = 50176 >= N_NODES
#define BPITCH  136   // u32 pitch for packed-bf16x2 W planes (conflict-free)

// ---------------- scratch (device globals; no allocation allowed) ----------------
__device__ float g_xbuf[N_NODES * DIM];   // current node features
__device__ float g_h   [N_NODES * DIM];   // hidden / predictor A
__device__ float g_aggr[N_NODES * DIM];   // x + message aggregation
__device__ float g_B   [N_NODES * DIM];   // predictor B
__device__ int   g_src [N_EDGES];
__device__ int   g_dst [N_EDGES];
__device__ int   g_ssrc[N_EDGES];         // src sorted by dst
__device__ float g_sea [N_EDGES];         // edge_attr sorted by dst
__device__ int   g_seid[N_EDGES];         // original edge id sorted by dst
__device__ int   g_deg [N_NODES];
__device__ int   g_row [N_NODES + 1];
__device__ int   g_cur [N_NODES];
__device__ int   g_bsum[SCAN_NB];
__device__ int   g_is64;

__device__ __forceinline__ float* bufptr(int id) {
    switch (id) {
        case 0:  return g_xbuf;
        case 1:  return g_h;
        case 2:  return g_aggr;
        default: return g_B;
    }
}

// ---------------- bf16 helpers ----------------
__device__ __forceinline__ uint32_t packbf(float vhi, float vlo) {
    uint32_t r;
    asm("cvt.rn.bf16x2.f32 %0, %1, %2;" : "=r"(r) : "f"(vhi), "f"(vlo));
    return r;
}
__device__ __forceinline__ void mma_bf16(float* c, const uint32_t* a,
                                         const uint32_t* b) {
    asm("mma.sync.aligned.m16n8k16.row.col.f32.bf16.bf16.f32 "
        "{%0,%1,%2,%3},{%4,%5,%6,%7},{%8,%9},{%0,%1,%2,%3};"
        : "+f"(c[0]), "+f"(c[1]), "+f"(c[2]), "+f"(c[3])
        : "r"(a[0]), "r"(a[1]), "r"(a[2]), "r"(a[3]), "r"(b[0]), "r"(b[1]));
}
// split a float2 (v0 = lower k, v1 = upper k) into bf16x2 hi + residual-lo words
__device__ __forceinline__ void split2(float2 v, uint32_t& hi, uint32_t& lo) {
    hi = packbf(v.y, v.x);
    float h0 = __uint_as_float(hi << 16);
    float h1 = __uint_as_float(hi & 0xffff0000u);
    lo = packbf(v.y - h1, v.x - h0);
}

// ---------------- dtype detect + index normalize ----------------
__global__ void k_detect(const void* ei) {
    __shared__ int s;
    if (threadIdx.x == 0) s = 0;
    __syncthreads();
    const unsigned* w = (const unsigned*)ei;
    if (w[2 * threadIdx.x + 1] != 0u) atomicOr(&s, 1);
    __syncthreads();
    if (threadIdx.x == 0) g_is64 = (s == 0) ? 1 : 0;
}

__global__ void k_convert(const void* ei) {
    int i = blockIdx.x * blockDim.x + threadIdx.x;
    if (i >= N_EDGES) return;
    if (g_is64) {
        const long long* p = (const long long*)ei;
        g_src[i] = (int)p[i];
        g_dst[i] = (int)p[N_EDGES + i];
    } else {
        const int* p = (const int*)ei;
        g_src[i] = p[i];
        g_dst[i] = p[N_EDGES + i];
    }
}

// ---------------- CSR build ----------------
__global__ void k_zero_deg() {
    int i = blockIdx.x * blockDim.x + threadIdx.x;
    if (i < N_NODES) g_deg[i] = 0;
}

__global__ void k_hist() {
    int i = blockIdx.x * blockDim.x + threadIdx.x;
    if (i < N_EDGES) atomicAdd(&g_deg[g_dst[i]], 1);
}

__global__ void k_scanA() {
    __shared__ int s[256];
    int t = threadIdx.x;
    int idx = blockIdx.x * 256 + t;
    int v = (idx < N_NODES) ? g_deg[idx] : 0;
    s[t] = v;
    __syncthreads();
    #pragma unroll
    for (int off = 1; off < 256; off <<= 1) {
        int add = (t >= off) ? s[t - off] : 0;
        __syncthreads();
        s[t] += add;
        __syncthreads();
    }
    int incl = s[t];
    if (idx < N_NODES) g_row[idx] = incl - v;
    if (t == 255) g_bsum[blockIdx.x] = incl;
}

__global__ void k_scanB() {
    __shared__ int s[256];
    int t = threadIdx.x;
    int v = (t < SCAN_NB) ? g_bsum[t] : 0;
    s[t] = v;
    __syncthreads();
    #pragma unroll
    for (int off = 1; off < 256; off <<= 1) {
        int add = (t >= off) ? s[t - off] : 0;
        __syncthreads();
        s[t] += add;
        __syncthreads();
    }
    if (t < SCAN_NB) g_bsum[t] = s[t] - v;  // exclusive
}

__global__ void k_scanC() {
    int idx = blockIdx.x * 256 + threadIdx.x;
    if (idx < N_NODES) {
        int r = g_row[idx] + g_bsum[blockIdx.x];
        g_row[idx] = r;
        g_cur[idx] = r;
    }
    if (idx == 0) g_row[N_NODES] = N_EDGES;
}

__global__ void k_scatter(const float* __restrict__ ea) {
    int e = blockIdx.x * blockDim.x + threadIdx.x;
    if (e >= N_EDGES) return;
    int d = g_dst[e];
    int pos = atomicAdd(&g_cur[d], 1);
    g_ssrc[pos] = g_src[e];
    g_sea[pos]  = ea[e];
    g_seid[pos] = e;
}

// ---------------- CSR aggregation ----------------
// aggr[n] = x[n] + sum_{e in row n} relu(x[src_e] + a_e*We + be); warp per node
__global__ void __launch_bounds__(256)
k_aggr(const float* __restrict__ xext,
       const float* __restrict__ We, const float* __restrict__ be) {
    int gt   = blockIdx.x * blockDim.x + threadIdx.x;
    int node = gt >> 5;
    int lane = gt & 31;
    if (node >= N_NODES) return;

    const float* xin = xext ? xext : g_xbuf;

    float4 wv = ((const float4*)We)[lane];
    float4 bv = ((const float4*)be)[lane];
    const float4* xv = (const float4*)xin;

    float4 acc = xv[(size_t)node * 32 + lane];   // (1+eps)*x, eps=0
    int j   = g_row[node];
    int end = g_row[node + 1];

    for (; j + 1 < end; j += 2) {
        int   s0 = __ldg(g_ssrc + j),     s1 = __ldg(g_ssrc + j + 1);
        float a0 = __ldg(g_sea + j),      a1 = __ldg(g_sea + j + 1);
        float4 x0 = xv[(size_t)s0 * 32 + lane];
        float4 x1 = xv[(size_t)s1 * 32 + lane];
        acc.x += fmaxf(x0.x + fmaf(a0, wv.x, bv.x), 0.f)
               + fmaxf(x1.x + fmaf(a1, wv.x, bv.x), 0.f);
        acc.y += fmaxf(x0.y + fmaf(a0, wv.y, bv.y), 0.f)
               + fmaxf(x1.y + fmaf(a1, wv.y, bv.y), 0.f);
        acc.z += fmaxf(x0.z + fmaf(a0, wv.z, bv.z), 0.f)
               + fmaxf(x1.z + fmaf(a1, wv.z, bv.z), 0.f);
        acc.w += fmaxf(x0.w + fmaf(a0, wv.w, bv.w), 0.f)
               + fmaxf(x1.w + fmaf(a1, wv.w, bv.w), 0.f);
    }
    if (j < end) {
        int   s0 = __ldg(g_ssrc + j);
        float a0 = __ldg(g_sea + j);
        float4 x0 = xv[(size_t)s0 * 32 + lane];
        acc.x += fmaxf(x0.x + fmaf(a0, wv.x, bv.x), 0.f);
        acc.y += fmaxf(x0.y + fmaf(a0, wv.y, bv.y), 0.f);
        acc.z += fmaxf(x0.z + fmaf(a0, wv.z, bv.z), 0.f);
        acc.w += fmaxf(x0.w + fmaf(a0, wv.w, bv.w), 0.f);
    }
    ((float4*)g_aggr)[(size_t)node * 32 + lane] = acc;
}

// ---------------- tensor-core GEMM: out = act(A @ W + bias), bf16x3 ----------------
__global__ void __launch_bounds__(256, 2)
k_gemm_tc(int ia, const float* __restrict__ W,
          const float* __restrict__ bias, int io, int relu, int nrows) {
    extern __shared__ uint32_t sWp[];          // 2 * 64 * BPITCH u32
    uint32_t* sHi = sWp;
    uint32_t* sLo = sWp + 64 * BPITCH;
    for (int i = threadIdx.x; i < 64 * 128; i += 256) {
        int k2 = i >> 7, n = i & 127;
        float v0 = __ldg(W + (2 * k2)     * DIM + n);
        float v1 = __ldg(W + (2 * k2 + 1) * DIM + n);
        uint32_t hi, lo;
        split2(make_float2(v0, v1), hi, lo);
        sHi[k2 * BPITCH + n] = hi;
        sLo[k2 * BPITCH + n] = lo;
    }
    __syncthreads();

    const float* A   = bufptr(ia);
    float*       out = bufptr(io);

    int warp = threadIdx.x >> 5, lane = threadIdx.x & 31;
    int g   = lane >> 2;    // 0..7
    int tid = lane & 3;     // 0..3
    int mbase = blockIdx.x * 128 + (warp >> 1) * 32;
    int nbase = (warp & 1) * 64;

    float acc[2][8][4];
    #pragma unroll
    for (int mt = 0; mt < 2; mt++)
        #pragma unroll
        for (int nt = 0; nt < 8; nt++)
            #pragma unroll
            for (int i = 0; i < 4; i++) acc[mt][nt][i] = 0.f;

    int r0[2], r1[2];
    #pragma unroll
    for (int mt = 0; mt < 2; mt++) {
        int a = mbase + mt * 16 + g;
        r0[mt] = min(a, nrows - 1);
        r1[mt] = min(a + 8, nrows - 1);
    }

    #pragma unroll 1
    for (int c0 = 0; c0 < 128; c0 += 16) {
        int kq = c0 + tid * 2;
        uint32_t ah[2][4], al[2][4];
        #pragma unroll
        for (int mt = 0; mt < 2; mt++) {
            float2 p00 = *(const float2*)(A + (size_t)r0[mt] * DIM + kq);
            float2 p10 = *(const float2*)(A + (size_t)r1[mt] * DIM + kq);
            float2 p01 = *(const float2*)(A + (size_t)r0[mt] * DIM + kq + 8);
            float2 p11 = *(const float2*)(A + (size_t)r1[mt] * DIM + kq + 8);
            split2(p00, ah[mt][0], al[mt][0]);
            split2(p10, ah[mt][1], al[mt][1]);
            split2(p01, ah[mt][2], al[mt][2]);
            split2(p11, ah[mt][3], al[mt][3]);
        }
        int kb = (c0 >> 1) + tid;   // word row in planes
        #pragma unroll
        for (int nh = 0; nh < 2; nh++) {
            uint32_t bh[4][2], bl[4][2];
            #pragma unroll
            for (int q = 0; q < 4; q++) {
                int col = nbase + (nh * 4 + q) * 8 + g;
                bh[q][0] = sHi[kb * BPITCH + col];
                bh[q][1] = sHi[(kb + 4) * BPITCH + col];
                bl[q][0] = sLo[kb * BPITCH + col];
                bl[q][1] = sLo[(kb + 4) * BPITCH + col];
            }
            #pragma unroll
            for (int mt = 0; mt < 2; mt++)
                #pragma unroll
                for (int q = 0; q < 4; q++) {
                    float* c = acc[mt][nh * 4 + q];
                    mma_bf16(c, al[mt], bh[q]);   // Al*Wh
                    mma_bf16(c, ah[mt], bl[q]);   // Ah*Wl
                    mma_bf16(c, ah[mt], bh[q]);   // Ah*Wh
                }
        }
    }

    #pragma unroll
    for (int mt = 0; mt < 2; mt++) {
        int ra = mbase + mt * 16 + g;
        int rb = ra + 8;
        #pragma unroll
        for (int nt = 0; nt < 8; nt++) {
            int c = nbase + nt * 8 + tid * 2;
            float b0 = bias ? __ldg(bias + c)     : 0.f;
            float b1 = bias ? __ldg(bias + c + 1) : 0.f;
            float v0 = acc[mt][nt][0] + b0, v1 = acc[mt][nt][1] + b1;
            float v2 = acc[mt][nt][2] + b0, v3 = acc[mt][nt][3] + b1;
            if (relu) {
                v0 = fmaxf(v0, 0.f); v1 = fmaxf(v1, 0.f);
                v2 = fmaxf(v2, 0.f); v3 = fmaxf(v3, 0.f);
            }
            if (ra < nrows) *(float2*)&out[(size_t)ra * DIM + c] = make_float2(v0, v1);
            if (rb < nrows) *(float2*)&out[(size_t)rb * DIM + c] = make_float2(v2, v3);
        }
    }
}

// ---------------- edge predictor, CSR order ----------------
// warp per node d: t = B[d] + bp1 (once); per incident edge gather A[src],
// p = relu(A[src]+t) . Wp2; shfl-reduce; out[eid] = p + bp2
__global__ void __launch_bounds__(256)
k_edge_pred_csr(const float* __restrict__ bp1,
                const float* __restrict__ Wp2,
                const float* __restrict__ bp2,
                float* __restrict__ out) {
    int gt   = blockIdx.x * blockDim.x + threadIdx.x;
    int node = gt >> 5;
    int lane = gt & 31;
    if (node >= N_NODES) return;

    float4 b1 = ((const float4*)bp1)[lane];
    float4 w2 = ((const float4*)Wp2)[lane];
    float  b2 = __ldg(bp2);

    float4 t = ((const float4*)(g_B + (size_t)node * DIM))[lane];
    t.x += b1.x; t.y += b1.y; t.z += b1.z; t.w += b1.w;

    const float4* av4 = (const float4*)g_h;
    int j   = g_row[node];
    int end = g_row[node + 1];

    for (; j + 1 < end; j += 2) {
        int s0 = __ldg(g_ssrc + j),  s1 = __ldg(g_ssrc + j + 1);
        int e0 = __ldg(g_seid + j),  e1 = __ldg(g_seid + j + 1);
        float4 a0 = av4[(size_t)s0 * 32 + lane];
        float4 a1 = av4[(size_t)s1 * 32 + lane];
        float p0 = 0.f, p1 = 0.f;
        p0 = fmaf(fmaxf(a0.x + t.x, 0.f), w2.x, p0);
        p0 = fmaf(fmaxf(a0.y + t.y, 0.f), w2.y, p0);
        p0 = fmaf(fmaxf(a0.z + t.z, 0.f), w2.z, p0);
        p0 = fmaf(fmaxf(a0.w + t.w, 0.f), w2.w, p0);
        p1 = fmaf(fmaxf(a1.x + t.x, 0.f), w2.x, p1);
        p1 = fmaf(fmaxf(a1.y + t.y, 0.f), w2.y, p1);
        p1 = fmaf(fmaxf(a1.z + t.z, 0.f), w2.z, p1);
        p1 = fmaf(fmaxf(a1.w + t.w, 0.f), w2.w, p1);
        #pragma unroll
        for (int o = 16; o > 0; o >>= 1) {
            p0 += __shfl_xor_sync(0xffffffffu, p0, o);
            p1 += __shfl_xor_sync(0xffffffffu, p1, o);
        }
        if (lane == 0) out[e0] = p0 + b2;
        if (lane == 1) out[e1] = p1 + b2;
    }
    if (j < end) {
        int s0 = __ldg(g_ssrc + j);
        int e0 = __ldg(g_seid + j);
        float4 a0 = av4[(size_t)s0 * 32 + lane];
        float p0 = 0.f;
        p0 = fmaf(fmaxf(a0.x + t.x, 0.f), w2.x, p0);
        p0 = fmaf(fmaxf(a0.y + t.y, 0.f), w2.y, p0);
        p0 = fmaf(fmaxf(a0.z + t.z, 0.f), w2.z, p0);
        p0 = fmaf(fmaxf(a0.w + t.w, 0.f), w2.w, p0);
        #pragma unroll
        for (int o = 16; o > 0; o >>= 1)
            p0 += __shfl_xor_sync(0xffffffffu, p0, o);
        if (lane == 0) out[e0] = p0 + b2;
    }
}

// ---------------- launch ----------------
extern "C" void kernel_launch(void* const* d_in, const int* in_sizes, int n_in,
                              void* d_out, int out_size) {
    const float* x   = (const float*)d_in[0];
    const float* ea  = (const float*)d_in[1];
    const void*  ei  = d_in[2];
    const float* Wl1 = (const float*)d_in[3];
    const float* bl1 = (const float*)d_in[4];
    const float* Wl2 = (const float*)d_in[5];
    const float* bl2 = (const float*)d_in[6];
    const float* We  = (const float*)d_in[7];
    const float* be  = (const float*)d_in[8];
    const float* Wp1 = (const float*)d_in[9];
    const float* bp1 = (const float*)d_in[10];
    const float* Wp2 = (const float*)d_in[11];
    const float* bp2 = (const float*)d_in[12];
    float* out = (float*)d_out;

    const int GEMM_SMEM = 2 * 64 * BPITCH * (int)sizeof(uint32_t);  // 69632
    cudaFuncSetAttribute(k_gemm_tc, cudaFuncAttributeMaxDynamicSharedMemorySize,
                         GEMM_SMEM);

    const int GEMM_GRID = (N_NODES + 127) / 128;         // 391
    const int EDGE_GRID = (N_EDGES + 255) / 256;         // 3125
    const int NODE_GRID = (N_NODES + 255) / 256;         // 196
    const int AGGR_GRID = (N_NODES * 32 + 255) / 256;    // 6250

    // index normalize + CSR build (once per call)
    k_detect<<<1, 64>>>(ei);
    k_convert<<<EDGE_GRID, 256>>>(ei);
    k_zero_deg<<<NODE_GRID, 256>>>();
    k_hist<<<EDGE_GRID, 256>>>();
    k_scanA<<<SCAN_NB, 256>>>();
    k_scanB<<<1, 256>>>();
    k_scanC<<<SCAN_NB, 256>>>();
    k_scatter<<<EDGE_GRID, 256>>>(ea);

    for (int l = 0; l < 3; l++) {
        // aggr = x + sum(msg);  layer 0 reads the external x directly
        k_aggr<<<AGGR_GRID, 256>>>((l == 0) ? x : nullptr,
                                   We + l * DIM, be + l * DIM);
        // h = relu(aggr @ Wl1 + bl1)
        k_gemm_tc<<<GEMM_GRID, 256, GEMM_SMEM>>>(2, Wl1 + l * DIM * DIM,
                                                 bl1 + l * DIM, 1, 1, N_NODES);
        // x = relu(h @ Wl2 + bl2)
        k_gemm_tc<<<GEMM_GRID, 256, GEMM_SMEM>>>(1, Wl2 + l * DIM * DIM,
                                                 bl2 + l * DIM, 0, 1, N_NODES);
    }

    // A = x @ Wp1[0:128] (g_h),  B = x @ Wp1[128:256] (g_B)
    k_gemm_tc<<<GEMM_GRID, 256, GEMM_SMEM>>>(0, Wp1, nullptr, 1, 0, N_NODES);
    k_gemm_tc<<<GEMM_GRID, 256, GEMM_SMEM>>>(0, Wp1 + DIM * DIM, nullptr, 3, 0, N_NODES);

    k_edge_pred_csr<<<AGGR_GRID, 256>>>(bp1, Wp2, bp2, out);
}

// round 8
// speedup vs baseline: 2.3578x; 1.0050x over previous
#include <cuda_runtime.h>
#include <cstdint>

#define N_NODES 50000
#define N_EDGES 800000
#define DIM     128
#define SCAN_NB 196   // 196*256 = 50176 >= N_NODES
#define BPITCH  136   // u32 pitch for packed-bf16x2 W planes (conflict-free)

// ---------------- scratch (device globals; no allocation allowed) ----------------
__device__ float g_xbuf[N_NODES * DIM];   // current node features
__device__ float g_h   [N_NODES * DIM];   // hidden / predictor A
__device__ float g_aggr[N_NODES * DIM];   // x + message aggregation
__device__ float g_B   [N_NODES * DIM];   // predictor B
__device__ int   g_ssrc[N_EDGES];         // src sorted by dst
__device__ float g_sea [N_EDGES];         // edge_attr sorted by dst
__device__ int   g_seid[N_EDGES];         // original edge id sorted by dst
__device__ int   g_deg [N_NODES];
__device__ int   g_row [N_NODES + 1];
__device__ int   g_cur [N_NODES];
__device__ int   g_bsum[SCAN_NB];
__device__ int   g_is64;

__device__ __forceinline__ float* bufptr(int id) {
    switch (id) {
        case 0:  return g_xbuf;
        case 1:  return g_h;
        case 2:  return g_aggr;
        default: return g_B;
    }
}

// ---------------- bf16 helpers ----------------
__device__ __forceinline__ uint32_t packbf(float vhi, float vlo) {
    uint32_t r;
    asm("cvt.rn.bf16x2.f32 %0, %1, %2;" : "=r"(r) : "f"(vhi), "f"(vlo));
    return r;
}
__device__ __forceinline__ void mma_bf16(float* c, const uint32_t* a,
                                         const uint32_t* b) {
    asm("mma.sync.aligned.m16n8k16.row.col.f32.bf16.bf16.f32 "
        "{%0,%1,%2,%3},{%4,%5,%6,%7},{%8,%9},{%0,%1,%2,%3};"
        : "+f"(c[0]), "+f"(c[1]), "+f"(c[2]), "+f"(c[3])
        : "r"(a[0]), "r"(a[1]), "r"(a[2]), "r"(a[3]), "r"(b[0]), "r"(b[1]));
}
// split a float2 (v0 = lower k, v1 = upper k) into bf16x2 hi + residual-lo words
__device__ __forceinline__ void split2(float2 v, uint32_t& hi, uint32_t& lo) {
    hi = packbf(v.y, v.x);
    float h0 = __uint_as_float(hi << 16);
    float h1 = __uint_as_float(hi & 0xffff0000u);
    lo = packbf(v.y - h1, v.x - h0);
}

// ---------------- edge-index access (dtype-agnostic) ----------------
__device__ __forceinline__ int ei_src(const void* ei, int e) {
    return g_is64 ? (int)((const long long*)ei)[e] : ((const int*)ei)[e];
}
__device__ __forceinline__ int ei_dst(const void* ei, int e) {
    return g_is64 ? (int)((const long long*)ei)[N_EDGES + e]
                  : ((const int*)ei)[N_EDGES + e];
}

// ---------------- dtype detect ----------------
__global__ void k_detect(const void* ei) {
    __shared__ int s;
    if (threadIdx.x == 0) s = 0;
    __syncthreads();
    const unsigned* w = (const unsigned*)ei;
    if (w[2 * threadIdx.x + 1] != 0u) atomicOr(&s, 1);
    __syncthreads();
    if (threadIdx.x == 0) g_is64 = (s == 0) ? 1 : 0;
}

// ---------------- CSR build ----------------
__global__ void k_zero_deg() {
    int i = blockIdx.x * blockDim.x + threadIdx.x;
    if (i < N_NODES) g_deg[i] = 0;
}

__global__ void k_hist(const void* ei) {
    int i = blockIdx.x * blockDim.x + threadIdx.x;
    if (i < N_EDGES) atomicAdd(&g_deg[ei_dst(ei, i)], 1);
}

__global__ void k_scanA() {
    __shared__ int s[256];
    int t = threadIdx.x;
    int idx = blockIdx.x * 256 + t;
    int v = (idx < N_NODES) ? g_deg[idx] : 0;
    s[t] = v;
    __syncthreads();
    #pragma unroll
    for (int off = 1; off < 256; off <<= 1) {
        int add = (t >= off) ? s[t - off] : 0;
        __syncthreads();
        s[t] += add;
        __syncthreads();
    }
    int incl = s[t];
    if (idx < N_NODES) g_row[idx] = incl - v;
    if (t == 255) g_bsum[blockIdx.x] = incl;
}

__global__ void k_scanB() {
    __shared__ int s[256];
    int t = threadIdx.x;
    int v = (t < SCAN_NB) ? g_bsum[t] : 0;
    s[t] = v;
    __syncthreads();
    #pragma unroll
    for (int off = 1; off < 256; off <<= 1) {
        int add = (t >= off) ? s[t - off] : 0;
        __syncthreads();
        s[t] += add;
        __syncthreads();
    }
    if (t < SCAN_NB) g_bsum[t] = s[t] - v;  // exclusive
}

__global__ void k_scanC() {
    int idx = blockIdx.x * 256 + threadIdx.x;
    if (idx < N_NODES) {
        int r = g_row[idx] + g_bsum[blockIdx.x];
        g_row[idx] = r;
        g_cur[idx] = r;
    }
    if (idx == 0) g_row[N_NODES] = N_EDGES;
}

__global__ void k_scatter(const void* ei, const float* __restrict__ ea) {
    int e = blockIdx.x * blockDim.x + threadIdx.x;
    if (e >= N_EDGES) return;
    int d = ei_dst(ei, e);
    int pos = atomicAdd(&g_cur[d], 1);
    g_ssrc[pos] = ei_src(ei, e);
    g_sea[pos]  = ea[e];
    g_seid[pos] = e;
}

// ---------------- CSR aggregation ----------------
// aggr[n] = x[n] + sum_{e in row n} relu(x[src_e] + a_e*We + be); warp per node
// 4-edge unroll for memory-level parallelism
__global__ void __launch_bounds__(256)
k_aggr(const float* __restrict__ xext,
       const float* __restrict__ We, const float* __restrict__ be) {
    int gt   = blockIdx.x * blockDim.x + threadIdx.x;
    int node = gt >> 5;
    int lane = gt & 31;
    if (node >= N_NODES) return;

    const float* xin = xext ? xext : g_xbuf;

    float4 wv = ((const float4*)We)[lane];
    float4 bv = ((const float4*)be)[lane];
    const float4* xv = (const float4*)xin;

    float4 acc = xv[(size_t)node * 32 + lane];   // (1+eps)*x, eps=0
    int j   = g_row[node];
    int end = g_row[node + 1];

    for (; j + 3 < end; j += 4) {
        int   s0 = __ldg(g_ssrc + j),     s1 = __ldg(g_ssrc + j + 1);
        int   s2 = __ldg(g_ssrc + j + 2), s3 = __ldg(g_ssrc + j + 3);
        float a0 = __ldg(g_sea + j),      a1 = __ldg(g_sea + j + 1);
        float a2 = __ldg(g_sea + j + 2),  a3 = __ldg(g_sea + j + 3);
        float4 x0 = xv[(size_t)s0 * 32 + lane];
        float4 x1 = xv[(size_t)s1 * 32 + lane];
        float4 x2 = xv[(size_t)s2 * 32 + lane];
        float4 x3 = xv[(size_t)s3 * 32 + lane];
        acc.x += fmaxf(x0.x + fmaf(a0, wv.x, bv.x), 0.f)
               + fmaxf(x1.x + fmaf(a1, wv.x, bv.x), 0.f)
               + fmaxf(x2.x + fmaf(a2, wv.x, bv.x), 0.f)
               + fmaxf(x3.x + fmaf(a3, wv.x, bv.x), 0.f);
        acc.y += fmaxf(x0.y + fmaf(a0, wv.y, bv.y), 0.f)
               + fmaxf(x1.y + fmaf(a1, wv.y, bv.y), 0.f)
               + fmaxf(x2.y + fmaf(a2, wv.y, bv.y), 0.f)
               + fmaxf(x3.y + fmaf(a3, wv.y, bv.y), 0.f);
        acc.z += fmaxf(x0.z + fmaf(a0, wv.z, bv.z), 0.f)
               + fmaxf(x1.z + fmaf(a1, wv.z, bv.z), 0.f)
               + fmaxf(x2.z + fmaf(a2, wv.z, bv.z), 0.f)
               + fmaxf(x3.z + fmaf(a3, wv.z, bv.z), 0.f);
        acc.w += fmaxf(x0.w + fmaf(a0, wv.w, bv.w), 0.f)
               + fmaxf(x1.w + fmaf(a1, wv.w, bv.w), 0.f)
               + fmaxf(x2.w + fmaf(a2, wv.w, bv.w), 0.f)
               + fmaxf(x3.w + fmaf(a3, wv.w, bv.w), 0.f);
    }
    for (; j < end; j++) {
        int   s0 = __ldg(g_ssrc + j);
        float a0 = __ldg(g_sea + j);
        float4 x0 = xv[(size_t)s0 * 32 + lane];
        acc.x += fmaxf(x0.x + fmaf(a0, wv.x, bv.x), 0.f);
        acc.y += fmaxf(x0.y + fmaf(a0, wv.y, bv.y), 0.f);
        acc.z += fmaxf(x0.z + fmaf(a0, wv.z, bv.z), 0.f);
        acc.w += fmaxf(x0.w + fmaf(a0, wv.w, bv.w), 0.f);
    }
    ((float4*)g_aggr)[(size_t)node * 32 + lane] = acc;
}

// ---------------- tensor-core GEMM: out = act(A @ W + bias), bf16x3 ----------------
__global__ void __launch_bounds__(256, 2)
k_gemm_tc(int ia, const float* __restrict__ W,
          const float* __restrict__ bias, int io, int relu, int nrows) {
    extern __shared__ uint32_t sWp[];          // 2 * 64 * BPITCH u32
    uint32_t* sHi = sWp;
    uint32_t* sLo = sWp + 64 * BPITCH;
    for (int i = threadIdx.x; i < 64 * 128; i += 256) {
        int k2 = i >> 7, n = i & 127;
        float v0 = __ldg(W + (2 * k2)     * DIM + n);
        float v1 = __ldg(W + (2 * k2 + 1) * DIM + n);
        uint32_t hi, lo;
        split2(make_float2(v0, v1), hi, lo);
        sHi[k2 * BPITCH + n] = hi;
        sLo[k2 * BPITCH + n] = lo;
    }
    __syncthreads();

    const float* A   = bufptr(ia);
    float*       out = bufptr(io);

    int warp = threadIdx.x >> 5, lane = threadIdx.x & 31;
    int g   = lane >> 2;    // 0..7
    int tid = lane & 3;     // 0..3
    int mbase = blockIdx.x * 128 + (warp >> 1) * 32;
    int nbase = (warp & 1) * 64;

    float acc[2][8][4];
    #pragma unroll
    for (int mt = 0; mt < 2; mt++)
        #pragma unroll
        for (int nt = 0; nt < 8; nt++)
            #pragma unroll
            for (int i = 0; i < 4; i++) acc[mt][nt][i] = 0.f;

    int r0[2], r1[2];
    #pragma unroll
    for (int mt = 0; mt < 2; mt++) {
        int a = mbase + mt * 16 + g;
        r0[mt] = min(a, nrows - 1);
        r1[mt] = min(a + 8, nrows - 1);
    }

    #pragma unroll 1
    for (int c0 = 0; c0 < 128; c0 += 16) {
        int kq = c0 + tid * 2;
        uint32_t ah[2][4], al[2][4];
        #pragma unroll
        for (int mt = 0; mt < 2; mt++) {
            float2 p00 = *(const float2*)(A + (size_t)r0[mt] * DIM + kq);
            float2 p10 = *(const float2*)(A + (size_t)r1[mt] * DIM + kq);
            float2 p01 = *(const float2*)(A + (size_t)r0[mt] * DIM + kq + 8);
            float2 p11 = *(const float2*)(A + (size_t)r1[mt] * DIM + kq + 8);
            split2(p00, ah[mt][0], al[mt][0]);
            split2(p10, ah[mt][1], al[mt][1]);
            split2(p01, ah[mt][2], al[mt][2]);
            split2(p11, ah[mt][3], al[mt][3]);
        }
        int kb = (c0 >> 1) + tid;   // word row in planes
        #pragma unroll
        for (int nh = 0; nh < 2; nh++) {
            uint32_t bh[4][2], bl[4][2];
            #pragma unroll
            for (int q = 0; q < 4; q++) {
                int col = nbase + (nh * 4 + q) * 8 + g;
                bh[q][0] = sHi[kb * BPITCH + col];
                bh[q][1] = sHi[(kb + 4) * BPITCH + col];
                bl[q][0] = sLo[kb * BPITCH + col];
                bl[q][1] = sLo[(kb + 4) * BPITCH + col];
            }
            #pragma unroll
            for (int mt = 0; mt < 2; mt++)
                #pragma unroll
                for (int q = 0; q < 4; q++) {
                    float* c = acc[mt][nh * 4 + q];
                    mma_bf16(c, al[mt], bh[q]);   // Al*Wh
                    mma_bf16(c, ah[mt], bl[q]);   // Ah*Wl
                    mma_bf16(c, ah[mt], bh[q]);   // Ah*Wh
                }
        }
    }

    #pragma unroll
    for (int mt = 0; mt < 2; mt++) {
        int ra = mbase + mt * 16 + g;
        int rb = ra + 8;
        #pragma unroll
        for (int nt = 0; nt < 8; nt++) {
            int c = nbase + nt * 8 + tid * 2;
            float b0 = bias ? __ldg(bias + c)     : 0.f;
            float b1 = bias ? __ldg(bias + c + 1) : 0.f;
            float v0 = acc[mt][nt][0] + b0, v1 = acc[mt][nt][1] + b1;
            float v2 = acc[mt][nt][2] + b0, v3 = acc[mt][nt][3] + b1;
            if (relu) {
                v0 = fmaxf(v0, 0.f); v1 = fmaxf(v1, 0.f);
                v2 = fmaxf(v2, 0.f); v3 = fmaxf(v3, 0.f);
            }
            if (ra < nrows) *(float2*)&out[(size_t)ra * DIM + c] = make_float2(v0, v1);
            if (rb < nrows) *(float2*)&out[(size_t)rb * DIM + c] = make_float2(v2, v3);
        }
    }
}

// ---------------- edge predictor, CSR order, 4-edge unroll ----------------
__global__ void __launch_bounds__(256)
k_edge_pred_csr(const float* __restrict__ bp1,
                const float* __restrict__ Wp2,
                const float* __restrict__ bp2,
                float* __restrict__ out) {
    int gt   = blockIdx.x * blockDim.x + threadIdx.x;
    int node = gt >> 5;
    int lane = gt & 31;
    if (node >= N_NODES) return;

    float4 b1 = ((const float4*)bp1)[lane];
    float4 w2 = ((const float4*)Wp2)[lane];
    float  b2 = __ldg(bp2);

    float4 t = ((const float4*)(g_B + (size_t)node * DIM))[lane];
    t.x += b1.x; t.y += b1.y; t.z += b1.z; t.w += b1.w;

    const float4* av4 = (const float4*)g_h;
    int j   = g_row[node];
    int end = g_row[node + 1];

    for (; j + 3 < end; j += 4) {
        int s0 = __ldg(g_ssrc + j),     s1 = __ldg(g_ssrc + j + 1);
        int s2 = __ldg(g_ssrc + j + 2), s3 = __ldg(g_ssrc + j + 3);
        int e0 = __ldg(g_seid + j),     e1 = __ldg(g_seid + j + 1);
        int e2 = __ldg(g_seid + j + 2), e3 = __ldg(g_seid + j + 3);
        float4 a0 = av4[(size_t)s0 * 32 + lane];
        float4 a1 = av4[(size_t)s1 * 32 + lane];
        float4 a2 = av4[(size_t)s2 * 32 + lane];
        float4 a3 = av4[(size_t)s3 * 32 + lane];
        float p0 = 0.f, p1 = 0.f, p2 = 0.f, p3 = 0.f;
        p0 = fmaf(fmaxf(a0.x + t.x, 0.f), w2.x, p0);
        p0 = fmaf(fmaxf(a0.y + t.y, 0.f), w2.y, p0);
        p0 = fmaf(fmaxf(a0.z + t.z, 0.f), w2.z, p0);
        p0 = fmaf(fmaxf(a0.w + t.w, 0.f), w2.w, p0);
        p1 = fmaf(fmaxf(a1.x + t.x, 0.f), w2.x, p1);
        p1 = fmaf(fmaxf(a1.y + t.y, 0.f), w2.y, p1);
        p1 = fmaf(fmaxf(a1.z + t.z, 0.f), w2.z, p1);
        p1 = fmaf(fmaxf(a1.w + t.w, 0.f), w2.w, p1);
        p2 = fmaf(fmaxf(a2.x + t.x, 0.f), w2.x, p2);
        p2 = fmaf(fmaxf(a2.y + t.y, 0.f), w2.y, p2);
        p2 = fmaf(fmaxf(a2.z + t.z, 0.f), w2.z, p2);
        p2 = fmaf(fmaxf(a2.w + t.w, 0.f), w2.w, p2);
        p3 = fmaf(fmaxf(a3.x + t.x, 0.f), w2.x, p3);
        p3 = fmaf(fmaxf(a3.y + t.y, 0.f), w2.y, p3);
        p3 = fmaf(fmaxf(a3.z + t.z, 0.f), w2.z, p3);
        p3 = fmaf(fmaxf(a3.w + t.w, 0.f), w2.w, p3);
        #pragma unroll
        for (int o = 16; o > 0; o >>= 1) {
            p0 += __shfl_xor_sync(0xffffffffu, p0, o);
            p1 += __shfl_xor_sync(0xffffffffu, p1, o);
            p2 += __shfl_xor_sync(0xffffffffu, p2, o);
            p3 += __shfl_xor_sync(0xffffffffu, p3, o);
        }
        if (lane == 0) out[e0] = p0 + b2;
        if (lane == 1) out[e1] = p1 + b2;
        if (lane == 2) out[e2] = p2 + b2;
        if (lane == 3) out[e3] = p3 + b2;
    }
    for (; j < end; j++) {
        int s0 = __ldg(g_ssrc + j);
        int e0 = __ldg(g_seid + j);
        float4 a0 = av4[(size_t)s0 * 32 + lane];
        float p0 = 0.f;
        p0 = fmaf(fmaxf(a0.x + t.x, 0.f), w2.x, p0);
        p0 = fmaf(fmaxf(a0.y + t.y, 0.f), w2.y, p0);
        p0 = fmaf(fmaxf(a0.z + t.z, 0.f), w2.z, p0);
        p0 = fmaf(fmaxf(a0.w + t.w, 0.f), w2.w, p0);
        #pragma unroll
        for (int o = 16; o > 0; o >>= 1)
            p0 += __shfl_xor_sync(0xffffffffu, p0, o);
        if (lane == 0) out[e0] = p0 + b2;
    }
}

// ---------------- launch ----------------
extern "C" void kernel_launch(void* const* d_in, const int* in_sizes, int n_in,
                              void* d_out, int out_size) {
    const float* x   = (const float*)d_in[0];
    const float* ea  = (const float*)d_in[1];
    const void*  ei  = d_in[2];
    const float* Wl1 = (const float*)d_in[3];
    const float* bl1 = (const float*)d_in[4];
    const float* Wl2 = (const float*)d_in[5];
    const float* bl2 = (const float*)d_in[6];
    const float* We  = (const float*)d_in[7];
    const float* be  = (const float*)d_in[8];
    const float* Wp1 = (const float*)d_in[9];
    const float* bp1 = (const float*)d_in[10];
    const float* Wp2 = (const float*)d_in[11];
    const float* bp2 = (const float*)d_in[12];
    float* out = (float*)d_out;

    const int GEMM_SMEM = 2 * 64 * BPITCH * (int)sizeof(uint32_t);  // 69632
    cudaFuncSetAttribute(k_gemm_tc, cudaFuncAttributeMaxDynamicSharedMemorySize,
                         GEMM_SMEM);

    const int GEMM_GRID = (N_NODES + 127) / 128;         // 391
    const int EDGE_GRID = (N_EDGES + 255) / 256;         // 3125
    const int NODE_GRID = (N_NODES + 255) / 256;         // 196
    const int AGGR_GRID = (N_NODES * 32 + 255) / 256;    // 6250

    // dtype detect + CSR build (once per call)
    k_detect<<<1, 64>>>(ei);
    k_zero_deg<<<NODE_GRID, 256>>>();
    k_hist<<<EDGE_GRID, 256>>>(ei);
    k_scanA<<<SCAN_NB, 256>>>();
    k_scanB<<<1, 256>>>();
    k_scanC<<<SCAN_NB, 256>>>();
    k_scatter<<<EDGE_GRID, 256>>>(ei, ea);

    for (int l = 0; l < 3; l++) {
        // aggr = x + sum(msg);  layer 0 reads the external x directly
        k_aggr<<<AGGR_GRID, 256>>>((l == 0) ? x : nullptr,
                                   We + l * DIM, be + l * DIM);
        // h = relu(aggr @ Wl1 + bl1)
        k_gemm_tc<<<GEMM_GRID, 256, GEMM_SMEM>>>(2, Wl1 + l * DIM * DIM,
                                                 bl1 + l * DIM, 1, 1, N_NODES);
        // x = relu(h @ Wl2 + bl2)
        k_gemm_tc<<<GEMM_GRID, 256, GEMM_SMEM>>>(1, Wl2 + l * DIM * DIM,
                                                 bl2 + l * DIM, 0, 1, N_NODES);
    }

    // A = x @ Wp1[0:128] (g_h),  B = x @ Wp1[128:256] (g_B)
    k_gemm_tc<<<GEMM_GRID, 256, GEMM_SMEM>>>(0, Wp1, nullptr, 1, 0, N_NODES);
    k_gemm_tc<<<GEMM_GRID, 256, GEMM_SMEM>>>(0, Wp1 + DIM * DIM, nullptr, 3, 0, N_NODES);

    k_edge_pred_csr<<<AGGR_GRID, 256>>>(bp1, Wp2, bp2, out);
}